// round 13
// baseline (speedup 1.0000x reference)
#include <cuda_runtime.h>
#include <cuda_bf16.h>
#include <math.h>
#include <stdint.h>

#define L_SEQ 1024
#define DM 768
#define DI 1536
#define DSTATE 16
#define DCONV 4
#define DTRANK 48
#define NLAYER 4
#define VOCAB 50280
#define VOCAB_PAD 50304            // 393*128
#define DBL_W (DTRANK + 2*DSTATE)  // 80
#define NCHUNK 16
#define LCHUNK (L_SEQ / NCHUNK)    // 64
#define XPJ_SPLITK 12
#define OPJ_SPLITK 6

// ---------------- scratch (device globals) ---------------------------------
__device__ float g_h [L_SEQ*DM];
__device__ float g_xz[L_SEQ*2*DI];
__device__ float g_xc[L_SEQ*DI];
__device__ float g_dbl[L_SEQ*DBL_W];
__device__ float g_dblp[XPJ_SPLITK * L_SEQ * DBL_W];
__device__ float g_dt[L_SEQ*DI];
__device__ float g_part[OPJ_SPLITK * L_SEQ * DM];

// chunked-scan state buffers
__device__ float g_sc_end [NCHUNK*DI*DSTATE];
__device__ float g_sc_prod[NCHUNK*DI*DSTATE];

// bf16 2-segment split buffers: row = [hi | lo], width 2K.
__device__ __nv_bfloat16 g_emb_s [(size_t)VOCAB_PAD * 2 * DM];
__device__ __nv_bfloat16 g_hn_s  [(size_t)L_SEQ * 2 * DM];
__device__ __nv_bfloat16 g_y_s   [(size_t)L_SEQ * 2 * DI];     // xc split, then y split
// per-layer weight splits (hoisted out of the layer loop)
__device__ __nv_bfloat16 g_inw_s [(size_t)NLAYER * 2*DI * 2*DM];
__device__ __nv_bfloat16 g_outw_s[(size_t)NLAYER * DM   * 2*DI];
__device__ __nv_bfloat16 g_xw_s  [(size_t)NLAYER * 128  * 2*DI];

__device__ __forceinline__ uint32_t s2u(const void* p){
    uint32_t a;
    asm("{ .reg .u64 t; cvta.to.shared.u64 t, %1; cvt.u32.u64 %0, t; }"
        : "=r"(a) : "l"(p));
    return a;
}

// ---------------- embedding gather ----------------------------------------
__global__ void embed_kernel(const int* __restrict__ ids,
                             const float* __restrict__ emb)
{
    int l = blockIdx.x;
    int id = ids[l];
    const float4* src = (const float4*)(emb + (size_t)id * DM);
    float4* dst = (float4*)(g_h + (size_t)l * DM);
    dst[threadIdx.x] = src[threadIdx.x];
}

// ---------------- rmsnorm (+ optional 6-way partial combine) + split -------
__global__ void rmsnorm_split_kernel(const float* __restrict__ parts,  // null = no combine
                                     __nv_bfloat16* __restrict__ out_s,
                                     const float* __restrict__ w)
{
    int l = blockIdx.x;
    float* hrow = g_h + (size_t)l * DM;
    __shared__ float xs[DM];
    const int S = L_SEQ * DM;

    float ss = 0.f;
    for (int i = threadIdx.x; i < DM; i += 256) {
        float v = hrow[i];
        if (parts) {
            int idx = l * DM + i;
            v += parts[idx] + parts[idx + S] + parts[idx + 2 * S]
               + parts[idx + 3 * S] + parts[idx + 4 * S] + parts[idx + 5 * S];
            hrow[i] = v;
        }
        xs[i] = v;
        ss = fmaf(v, v, ss);
    }
    #pragma unroll
    for (int off = 16; off >= 1; off >>= 1)
        ss += __shfl_xor_sync(0xffffffffu, ss, off);

    __shared__ float red[8];
    __shared__ float scale_s;
    int warp = threadIdx.x >> 5, lane = threadIdx.x & 31;
    if (lane == 0) red[warp] = ss;
    __syncthreads();
    if (threadIdx.x == 0) {
        float t = 0.f;
        #pragma unroll
        for (int i = 0; i < 8; i++) t += red[i];
        scale_s = rsqrtf(t / (float)DM + 1e-5f);
    }
    __syncthreads();
    float scale = scale_s;
    __nv_bfloat16* row = out_s + (size_t)l * 2 * DM;
    for (int i = threadIdx.x; i < DM; i += 256) {
        float v = xs[i] * scale * w[i];
        __nv_bfloat16 h = __float2bfloat16(v);
        __nv_bfloat16 lo = __float2bfloat16(v - __bfloat162float(h));
        row[i]      = h;
        row[DM + i] = lo;
    }
}

// ---------------- vectorized [h|l] split -----------------------------------
__device__ __forceinline__ uint32_t pack_bf(__nv_bfloat16 a, __nv_bfloat16 b){
    return (uint32_t)__bfloat16_as_ushort(a) |
           ((uint32_t)__bfloat16_as_ushort(b) << 16);
}

__global__ void split2_kernel(const float* __restrict__ src,
                              __nv_bfloat16* __restrict__ dst,
                              int R, int K, long long total4)
{
    long long idx = (long long)blockIdx.x * blockDim.x + threadIdx.x;
    if (idx >= total4) return;
    int kq = K >> 2;
    int r  = (int)(idx / kq);
    int k4 = (int)(idx - (long long)r * kq);
    float4 v = (r < R) ? ((const float4*)(src + (size_t)r * K))[k4]
                       : make_float4(0.f, 0.f, 0.f, 0.f);
    __nv_bfloat16 h0 = __float2bfloat16(v.x), h1 = __float2bfloat16(v.y);
    __nv_bfloat16 h2 = __float2bfloat16(v.z), h3 = __float2bfloat16(v.w);
    __nv_bfloat16 l0 = __float2bfloat16(v.x - __bfloat162float(h0));
    __nv_bfloat16 l1 = __float2bfloat16(v.y - __bfloat162float(h1));
    __nv_bfloat16 l2 = __float2bfloat16(v.z - __bfloat162float(h2));
    __nv_bfloat16 l3 = __float2bfloat16(v.w - __bfloat162float(h3));
    __nv_bfloat16* row = dst + (size_t)r * 2 * K;
    *(uint2*)(row + 4 * k4)     = make_uint2(pack_bf(h0, h1), pack_bf(h2, h3));
    *(uint2*)(row + K + 4 * k4) = make_uint2(pack_bf(l0, l1), pack_bf(l2, l3));
}

// x_proj weights: per layer, pad 80 -> 128 rows, split [h|l]
__global__ void split2_xw_kernel(const float* __restrict__ xw)
{
    long long idx = (long long)blockIdx.x * blockDim.x + threadIdx.x;   // < 4*128*DI/4
    int kq = DI >> 2;
    int rg = (int)(idx / kq);
    int k4 = (int)(idx - (long long)rg * kq);
    int layer = rg >> 7;
    int r     = rg & 127;
    float4 v = (r < DBL_W)
             ? ((const float4*)(xw + (size_t)layer * DBL_W * DI + (size_t)r * DI))[k4]
             : make_float4(0.f, 0.f, 0.f, 0.f);
    __nv_bfloat16 h0 = __float2bfloat16(v.x), h1 = __float2bfloat16(v.y);
    __nv_bfloat16 h2 = __float2bfloat16(v.z), h3 = __float2bfloat16(v.w);
    __nv_bfloat16 l0 = __float2bfloat16(v.x - __bfloat162float(h0));
    __nv_bfloat16 l1 = __float2bfloat16(v.y - __bfloat162float(h1));
    __nv_bfloat16 l2 = __float2bfloat16(v.z - __bfloat162float(h2));
    __nv_bfloat16 l3 = __float2bfloat16(v.w - __bfloat162float(h3));
    __nv_bfloat16* row = g_xw_s + (size_t)rg * 2 * DI;
    *(uint2*)(row + 4 * k4)      = make_uint2(pack_bf(h0, h1), pack_bf(h2, h3));
    *(uint2*)(row + DI + 4 * k4) = make_uint2(pack_bf(l0, l1), pack_bf(l2, l3));
}

// ---------------- depthwise causal conv + bias + silu + fused xc split -----
__global__ void conv_silu_kernel(const float* __restrict__ cw,
                                 const float* __restrict__ cb)
{
    int idx = blockIdx.x * blockDim.x + threadIdx.x;
    int l = idx / DI;
    int d = idx - l * DI;
    float4 wv = *(const float4*)(cw + (size_t)d * 4);
    float acc = cb[d];
    const float* wj = (const float*)&wv;
    #pragma unroll
    for (int j = 0; j < DCONV; j++) {
        int ll = l - (DCONV - 1) + j;
        if (ll >= 0) acc = fmaf(wj[j], g_xz[(size_t)ll * 2 * DI + d], acc);
    }
    acc = acc / (1.f + __expf(-acc));
    g_xc[idx] = acc;
    __nv_bfloat16 h = __float2bfloat16(acc);
    __nv_bfloat16 lo = __float2bfloat16(acc - __bfloat162float(h));
    __nv_bfloat16* row = g_y_s + (size_t)l * 2 * DI;
    row[d]      = h;
    row[DI + d] = lo;
}

// ---------------- chunked selective scan -----------------------------------
__global__ void scan_pass1_kernel(const float* __restrict__ A_log)
{
    int gw   = threadIdx.x >> 5;
    int lane = threadIdx.x & 31;
    int n    = lane & 15;
    int ch   = (blockIdx.x * 4 + gw) * 2 + (lane >> 4);
    int c    = blockIdx.y;

    float Aval = -__expf(A_log[(size_t)ch * DSTATE + n]);
    float s = 0.f, prod = 1.f;
    int l0 = c * LCHUNK;
    for (int l = l0; l < l0 + LCHUNK; l++) {
        float dtv = g_dt [(size_t)l * DI + ch];
        float xcv = g_xc [(size_t)l * DI + ch];
        float Bv  = g_dbl[(size_t)l * DBL_W + DTRANK + n];
        float dA  = __expf(dtv * Aval);
        s = dA * s + dtv * Bv * xcv;
        prod *= dA;
    }
    int idx = (c * DI + ch) * DSTATE + n;
    g_sc_end[idx]  = s;
    g_sc_prod[idx] = prod;
}

// pass2: inline prefix chain, replay, fused y-epilogue + bf16 split.
__global__ void scan_pass2_kernel(const float* __restrict__ A_log,
                                  const float* __restrict__ Dp)
{
    int gw   = threadIdx.x >> 5;
    int lane = threadIdx.x & 31;
    int n    = lane & 15;
    int ch   = (blockIdx.x * 4 + gw) * 2 + (lane >> 4);
    int c    = blockIdx.y;

    float Aval = -__expf(A_log[(size_t)ch * DSTATE + n]);

    // prefix chain over earlier chunks (this thread's (ch,n) lane only)
    float s = 0.f;
    for (int cc = 0; cc < c; cc++) {
        int id = (cc * DI + ch) * DSTATE + n;
        s = g_sc_prod[id] * s + g_sc_end[id];
    }

    float Dv = Dp[ch];
    int l0 = c * LCHUNK;
    for (int l = l0; l < l0 + LCHUNK; l++) {
        float dtv = g_dt [(size_t)l * DI + ch];
        float xcv = g_xc [(size_t)l * DI + ch];
        float Bv  = g_dbl[(size_t)l * DBL_W + DTRANK + n];
        float Cv  = g_dbl[(size_t)l * DBL_W + DTRANK + DSTATE + n];
        s = __expf(dtv * Aval) * s + dtv * Bv * xcv;
        float p = s * Cv;
        p += __shfl_xor_sync(0xffffffffu, p, 1);
        p += __shfl_xor_sync(0xffffffffu, p, 2);
        p += __shfl_xor_sync(0xffffffffu, p, 4);
        p += __shfl_xor_sync(0xffffffffu, p, 8);
        if (n == 0) {
            float z  = g_xz[(size_t)l * 2 * DI + DI + ch];
            float yv = (p + xcv * Dv) * (z / (1.f + __expf(-z)));
            __nv_bfloat16 h = __float2bfloat16(yv);
            __nv_bfloat16 lo = __float2bfloat16(yv - __bfloat162float(h));
            __nv_bfloat16* row = g_y_s + (size_t)l * 2 * DI;
            row[ch]      = h;
            row[DI + ch] = lo;
        }
    }
}

// ---------------- x_proj split-K combine ------------------------------------
__global__ void combine_dbl_kernel()
{
    int idx = blockIdx.x * blockDim.x + threadIdx.x;
    const int S = L_SEQ * DBL_W;
    float a = 0.f;
    #pragma unroll
    for (int z = 0; z < XPJ_SPLITK; z++) a += g_dblp[z * S + idx];
    g_dbl[idx] = a;
}

// ---------------- fp32 TN GEMM (dt_proj only) ------------------------------
#define GBM 128
#define GBN 64
#define GBK 16

template<int EPI>
__global__ __launch_bounds__(256)
void gemm_tn(const float* __restrict__ A, int lda,
             const float* __restrict__ B, int ldb,
             float* __restrict__ C, int ldc,
             int N, int K, const float* __restrict__ bias)
{
    __shared__ float As[GBK][GBM + 4];
    __shared__ float Bs[GBK][GBN + 4];

    const int bm  = blockIdx.y * GBM;
    const int bn  = blockIdx.x * GBN;
    const int tid = threadIdx.x;
    const int tx  = tid & 15;
    const int ty  = tid >> 4;
    const int a_row = tid >> 1;
    const int a_k   = (tid & 1) * 8;
    const int b_row = tid >> 2;
    const int b_k   = (tid & 3) * 4;

    float acc[8][4];
    #pragma unroll
    for (int i = 0; i < 8; i++)
        #pragma unroll
        for (int j = 0; j < 4; j++) acc[i][j] = 0.f;

    const float* Aptr = A + (size_t)(bm + a_row) * lda + a_k;
    const int gbn = bn + b_row;
    const float* Bptr = (gbn < N) ? (B + (size_t)gbn * ldb + b_k) : 0;

    for (int k0 = 0; k0 < K; k0 += GBK) {
        float4 av0 = *(const float4*)(Aptr + k0);
        float4 av1 = *(const float4*)(Aptr + k0 + 4);
        float4 bv  = Bptr ? *(const float4*)(Bptr + k0)
                          : make_float4(0.f, 0.f, 0.f, 0.f);

        As[a_k + 0][a_row] = av0.x; As[a_k + 1][a_row] = av0.y;
        As[a_k + 2][a_row] = av0.z; As[a_k + 3][a_row] = av0.w;
        As[a_k + 4][a_row] = av1.x; As[a_k + 5][a_row] = av1.y;
        As[a_k + 6][a_row] = av1.z; As[a_k + 7][a_row] = av1.w;
        Bs[b_k + 0][b_row] = bv.x;  Bs[b_k + 1][b_row] = bv.y;
        Bs[b_k + 2][b_row] = bv.z;  Bs[b_k + 3][b_row] = bv.w;
        __syncthreads();

        #pragma unroll
        for (int kk = 0; kk < GBK; kk++) {
            float ar[8], br[4];
            #pragma unroll
            for (int i = 0; i < 8; i++) ar[i] = As[kk][ty * 8 + i];
            #pragma unroll
            for (int j = 0; j < 4; j++) br[j] = Bs[kk][tx * 4 + j];
            #pragma unroll
            for (int i = 0; i < 8; i++)
                #pragma unroll
                for (int j = 0; j < 4; j++)
                    acc[i][j] = fmaf(ar[i], br[j], acc[i][j]);
        }
        __syncthreads();
    }

    #pragma unroll
    for (int i = 0; i < 8; i++) {
        int m = bm + ty * 8 + i;
        #pragma unroll
        for (int j = 0; j < 4; j++) {
            int n = bn + tx * 4 + j;
            if (n < N) {
                float v = acc[i][j];
                if (EPI == 1) {
                    v += bias[n];
                    v = fmaxf(v, 0.f) + log1pf(__expf(-fabsf(v)));
                }
                C[(size_t)m * ldc + n] = v;
            }
        }
    }
}

// ---------------- bf16 HMMA GEMM, templated N tile, 4-stage pair loop ------
#define TCM 128
#define TCK 32

__device__ __forceinline__ void cp_async16(uint32_t s, const void* g)
{
    asm volatile("cp.async.cg.shared.global [%0], [%1], 16;\n"
                 :: "r"(s), "l"(g));
}
__device__ __forceinline__ void cp_commit(){ asm volatile("cp.async.commit_group;\n" ::: "memory"); }
template<int N> __device__ __forceinline__ void cp_wait(){ asm volatile("cp.async.wait_group %0;\n" :: "n"(N) : "memory"); }

__device__ __forceinline__ void ldsm_x4(uint32_t* r, uint32_t addr)
{
    asm volatile("ldmatrix.sync.aligned.m8n8.x4.shared.b16 {%0,%1,%2,%3}, [%4];"
                 : "=r"(r[0]), "=r"(r[1]), "=r"(r[2]), "=r"(r[3]) : "r"(addr));
}
__device__ __forceinline__ void mma16816(float* c, const uint32_t* a, const uint32_t* b)
{
    asm volatile(
        "mma.sync.aligned.m16n8k16.row.col.f32.bf16.bf16.f32 "
        "{%0,%1,%2,%3}, {%4,%5,%6,%7}, {%8,%9}, {%0,%1,%2,%3};"
        : "+f"(c[0]), "+f"(c[1]), "+f"(c[2]), "+f"(c[3])
        : "r"(a[0]), "r"(a[1]), "r"(a[2]), "r"(a[3]), "r"(b[0]), "r"(b[1]));
}

__device__ __forceinline__ uint32_t swz(int row, int chunk){
    return (uint32_t)(row * 64 + ((chunk ^ ((row >> 1) & 3)) * 16));
}

template<int TN>
__global__ __launch_bounds__(TN == 64 ? 128 : 256, TN == 64 ? 4 : 2)
void mma_gemm(const __nv_bfloat16* __restrict__ A,
              const __nv_bfloat16* __restrict__ B,
              float* __restrict__ C, int ldc, int N, int Kreal,
              int cps, long long partStride)
{
    constexpr int NT   = (TN == 64) ? 128 : 256;
    constexpr int ASZ  = TCM * 64;
    constexpr int BSZ  = TN * 64;
    constexpr int STG  = ASZ + BSZ;
    constexpr int AI   = (TCM * 4) / NT;
    constexpr int BI   = (TN * 4) / NT;

    extern __shared__ __align__(16) char sm[];
    const uint32_t sbase = s2u(sm);
    const int tid  = threadIdx.x;
    const int wid  = tid >> 5, lane = tid & 31;
    const int wm   = wid & 1;
    const int wn   = wid >> 1;
    const int bm   = blockIdx.x * TCM;
    const int bn   = blockIdx.y * TN;
    const int KC   = Kreal / TCK;
    const int c0   = blockIdx.z * cps;
    const int c1   = c0 + cps;
    C += (long long)blockIdx.z * partStride;

    const int lda = 2 * Kreal;

    const __nv_bfloat16* Ag[AI]; uint32_t sa[AI];
    #pragma unroll
    for (int i = 0; i < AI; i++) {
        int v = tid + i * NT, r = v >> 2, k8 = v & 3;
        Ag[i] = A + (size_t)(bm + r) * lda + k8 * 8;
        sa[i] = sbase + swz(r, k8);
    }
    const __nv_bfloat16* Bg[BI]; uint32_t sb[BI];
    #pragma unroll
    for (int i = 0; i < BI; i++) {
        int v = tid + i * NT, r = v >> 2, k8 = v & 3;
        Bg[i] = B + (size_t)(bn + r) * lda + k8 * 8;
        sb[i] = sbase + ASZ + swz(r, k8);
    }

    float acc[4][4][4];
    #pragma unroll
    for (int i = 0; i < 4; i++)
        #pragma unroll
        for (int j = 0; j < 4; j++)
            #pragma unroll
            for (int t = 0; t < 4; t++) acc[i][j][t] = 0.f;

    const int a_row = wm * 64 + (lane & 15);
    const int a_k8s = lane >> 4;
    const int b_row = wn * 32 + (lane & 7) + ((lane >> 4) << 3);
    const int b_k8s = (lane >> 3) & 1;

    #define LOAD_STAGE(cc) do { \
        uint32_t so = (uint32_t)(((cc) - c0) & 3) * STG; \
        int ac = ((cc) < 2*KC ? (cc) : (cc) - 2*KC) * TCK; \
        int bc = ((cc) < KC   ? (cc) : (cc) - KC)   * TCK; \
        _Pragma("unroll") \
        for (int i = 0; i < AI; i++) cp_async16(sa[i] + so, Ag[i] + ac); \
        _Pragma("unroll") \
        for (int i = 0; i < BI; i++) cp_async16(sb[i] + so, Bg[i] + bc); \
        cp_commit(); \
    } while (0)

    #define MATH_STAGE(cc) do { \
        const uint32_t sA = sbase + (uint32_t)(((cc) - c0) & 3) * STG; \
        const uint32_t sB = sA + ASZ; \
        _Pragma("unroll") \
        for (int k16 = 0; k16 < 2; k16++) { \
            uint32_t afrag[4][4]; \
            _Pragma("unroll") \
            for (int mt = 0; mt < 4; mt++) { \
                int row = a_row + mt * 16; \
                ldsm_x4(afrag[mt], sA + swz(row, k16 * 2 + a_k8s)); \
            } \
            uint32_t bfrag[4][2]; \
            _Pragma("unroll") \
            for (int np = 0; np < 2; np++) { \
                int row = b_row + np * 16; \
                uint32_t t[4]; \
                ldsm_x4(t, sB + swz(row, k16 * 2 + b_k8s)); \
                bfrag[np * 2 + 0][0] = t[0]; bfrag[np * 2 + 0][1] = t[1]; \
                bfrag[np * 2 + 1][0] = t[2]; bfrag[np * 2 + 1][1] = t[3]; \
            } \
            _Pragma("unroll") \
            for (int mt = 0; mt < 4; mt++) \
                _Pragma("unroll") \
                for (int nt = 0; nt < 4; nt++) \
                    mma16816(acc[mt][nt], afrag[mt], bfrag[nt]); \
        } \
    } while (0)

    LOAD_STAGE(c0);
    if (c1 - c0 > 1) LOAD_STAGE(c0 + 1);

    for (int c = c0; c < c1; c += 2) {
        cp_wait<0>();
        __syncthreads();
        if (c + 2 < c1) { LOAD_STAGE(c + 2); LOAD_STAGE(c + 3); }
        MATH_STAGE(c);
        MATH_STAGE(c + 1);
    }
    #undef LOAD_STAGE
    #undef MATH_STAGE

    const int erow = lane >> 2;
    const int ecol = (lane & 3) * 2;
    #pragma unroll
    for (int mt = 0; mt < 4; mt++) {
        #pragma unroll
        for (int nt = 0; nt < 4; nt++) {
            int m0 = bm + wm * 64 + mt * 16 + erow;
            int n0 = bn + wn * 32 + nt * 8 + ecol;
            if (n0 < N) {
                float* p0 = C + (size_t)m0 * ldc + n0;
                float* p1 = p0 + 8 * ldc;
                *(float2*)p0 = make_float2(acc[mt][nt][0], acc[mt][nt][1]);
                *(float2*)p1 = make_float2(acc[mt][nt][2], acc[mt][nt][3]);
            }
        }
    }
}

#define SMEM64  (4 * (TCM*64 + 64*64))    // 49152
#define SMEM128 (4 * (TCM*64 + 128*64))   // 65536

// ---------------- orchestration --------------------------------------------
extern "C" void kernel_launch(void* const* d_in, const int* in_sizes, int n_in,
                              void* d_out, int out_size)
{
    const int*   ids        = (const int*)  d_in[0];
    const float* emb        = (const float*)d_in[1];
    const float* in_proj_w  = (const float*)d_in[2];
    const float* conv_w     = (const float*)d_in[3];
    const float* conv_b     = (const float*)d_in[4];
    const float* x_proj_w   = (const float*)d_in[5];
    const float* dt_proj_w  = (const float*)d_in[6];
    const float* dt_proj_b  = (const float*)d_in[7];
    const float* A_log      = (const float*)d_in[8];
    const float* D_param    = (const float*)d_in[9];
    const float* out_proj_w = (const float*)d_in[10];
    const float* norm_w     = (const float*)d_in[11];
    const float* norm_f_w   = (const float*)d_in[12];
    float* logits = (float*)d_out;

    cudaFuncSetAttribute(mma_gemm<64>,
                         cudaFuncAttributeMaxDynamicSharedMemorySize, SMEM64);
    cudaFuncSetAttribute(mma_gemm<128>,
                         cudaFuncAttributeMaxDynamicSharedMemorySize, SMEM128);

    float *xz, *xc, *dbl, *dblp, *dt, *part;
    cudaGetSymbolAddress((void**)&xz,   g_xz);
    cudaGetSymbolAddress((void**)&xc,   g_xc);
    cudaGetSymbolAddress((void**)&dbl,  g_dbl);
    cudaGetSymbolAddress((void**)&dblp, g_dblp);
    cudaGetSymbolAddress((void**)&dt,   g_dt);
    cudaGetSymbolAddress((void**)&part, g_part);

    __nv_bfloat16 *emb_s, *hn_s, *inw_s, *y_s, *outw_s, *xw_s;
    cudaGetSymbolAddress((void**)&emb_s,  g_emb_s);
    cudaGetSymbolAddress((void**)&hn_s,   g_hn_s);
    cudaGetSymbolAddress((void**)&inw_s,  g_inw_s);
    cudaGetSymbolAddress((void**)&y_s,    g_y_s);
    cudaGetSymbolAddress((void**)&outw_s, g_outw_s);
    cudaGetSymbolAddress((void**)&xw_s,   g_xw_s);

    embed_kernel<<<L_SEQ, DM / 4>>>(ids, emb);

    // ---- batched weight/embedding splits (independent of layer state) ----
    {
        long long t1 = (long long)NLAYER * 2 * DI * DM / 4;
        split2_kernel<<<(unsigned)((t1 + 255) / 256), 256>>>(
            in_proj_w, inw_s, NLAYER * 2 * DI, DM, t1);

        long long t2 = (long long)NLAYER * DM * DI / 4;
        split2_kernel<<<(unsigned)((t2 + 255) / 256), 256>>>(
            out_proj_w, outw_s, NLAYER * DM, DI, t2);

        long long t3 = (long long)NLAYER * 128 * DI / 4;
        split2_xw_kernel<<<(unsigned)((t3 + 255) / 256), 256>>>(x_proj_w);

        long long t4 = (long long)VOCAB_PAD * DM / 4;
        split2_kernel<<<(unsigned)((t4 + 255) / 256), 256>>>(
            emb, emb_s, VOCAB, DM, t4);
    }

    for (int i = 0; i < NLAYER; i++) {
        // rmsnorm (+combine previous layer's out_proj partials) + split
        rmsnorm_split_kernel<<<L_SEQ, 256>>>(i == 0 ? (const float*)0 : part,
                                             hn_s, norm_w + (size_t)i * DM);

        // xz = hn @ in_proj_w^T
        {
            dim3 g1(L_SEQ / TCM, 2 * DI / 64, 1);
            mma_gemm<64><<<g1, 128, SMEM64>>>(
                hn_s, inw_s + (size_t)i * 2 * DI * 2 * DM,
                xz, 2 * DI, 2 * DI, DM, 3 * (DM / TCK), 0);
        }

        conv_silu_kernel<<<(L_SEQ * DI) / 256, 256>>>(
            conv_w + (size_t)i * DI * DCONV, conv_b + (size_t)i * DI);

        // dbl = xc @ x_proj_w^T  (split-K=12, cps=12)
        {
            dim3 g2(L_SEQ / TCM, 2, XPJ_SPLITK);
            mma_gemm<64><<<g2, 128, SMEM64>>>(
                y_s, xw_s + (size_t)i * 128 * 2 * DI,
                dblp, DBL_W, DBL_W, DI,
                3 * (DI / TCK) / XPJ_SPLITK, (long long)L_SEQ * DBL_W);
        }
        combine_dbl_kernel<<<(L_SEQ * DBL_W) / 256, 256>>>();

        // dt = softplus(dbl[:, :48] @ dt_proj_w^T + b)
        {
            dim3 g3((DI + GBN - 1) / GBN, L_SEQ / GBM);
            gemm_tn<1><<<g3, 256>>>(dbl, DBL_W,
                                    dt_proj_w + (size_t)i * DI * DTRANK, DTRANK,
                                    dt, DI, DI, DTRANK,
                                    dt_proj_b + (size_t)i * DI);
        }

        // chunked selective scan (pass2 fuses prefix chain + y epilogue)
        {
            const float* Al = A_log + (size_t)i * DI * DSTATE;
            dim3 gs(DI / 8, NCHUNK);
            scan_pass1_kernel<<<gs, 128>>>(Al);
            scan_pass2_kernel<<<gs, 128>>>(Al, D_param + (size_t)i * DI);
        }

        // part[z] = y @ out_proj_w^T, split-K=6 (cps=24)
        {
            dim3 g4(L_SEQ / TCM, DM / 64, OPJ_SPLITK);
            mma_gemm<64><<<g4, 128, SMEM64>>>(
                y_s, outw_s + (size_t)i * DM * 2 * DI,
                part, DM, DM, DI,
                3 * (DI / TCK) / OPJ_SPLITK, (long long)L_SEQ * DM);
        }
    }

    // final rmsnorm combines last layer's partials
    rmsnorm_split_kernel<<<L_SEQ, 256>>>(part, hn_s, norm_f_w);

    // logits = hn @ emb^T — TN=128 tile
    {
        dim3 g5(L_SEQ / TCM, VOCAB_PAD / 128, 1);
        mma_gemm<128><<<g5, 256, SMEM128>>>(hn_s, emb_s, logits, VOCAB, VOCAB, DM,
                                            3 * (DM / TCK), 0);
    }
}

// round 14
// speedup vs baseline: 1.0597x; 1.0597x over previous
#include <cuda_runtime.h>
#include <cuda_bf16.h>
#include <math.h>
#include <stdint.h>

#define L_SEQ 1024
#define DM 768
#define DI 1536
#define DSTATE 16
#define DCONV 4
#define DTRANK 48
#define NLAYER 4
#define VOCAB 50280
#define VOCAB_PAD 50304            // 393*128
#define DBL_W (DTRANK + 2*DSTATE)  // 80
#define NCHUNK 16
#define LCHUNK (L_SEQ / NCHUNK)    // 64
#define XPJ_SPLITK 9

// ---------------- scratch (device globals) ---------------------------------
__device__ float g_h [L_SEQ*DM];
__device__ float g_xz[L_SEQ*2*DI];
__device__ float g_xc[L_SEQ*DI];
__device__ float g_dbl[L_SEQ*DBL_W];
__device__ float g_dblp[XPJ_SPLITK * L_SEQ * DBL_W];
__device__ float g_dt[L_SEQ*DI];
__device__ float g_y [L_SEQ*DI];
__device__ float g_part[6 * L_SEQ * DM];

// chunked-scan state buffers
__device__ float g_sc_end [NCHUNK*DI*DSTATE];
__device__ float g_sc_prod[NCHUNK*DI*DSTATE];
__device__ float g_sc_start[NCHUNK*DI*DSTATE];

// bf16 2-segment split buffers: row = [hi | lo], width 2K.
__device__ __nv_bfloat16 g_emb_s [(size_t)VOCAB_PAD * 2 * DM];
__device__ __nv_bfloat16 g_hn_s  [(size_t)L_SEQ * 2 * DM];
__device__ __nv_bfloat16 g_y_s   [(size_t)L_SEQ * 2 * DI];
// per-layer weight splits (hoisted, batched)
__device__ __nv_bfloat16 g_inw_s [(size_t)NLAYER * 2*DI * 2*DM];
__device__ __nv_bfloat16 g_outw_s[(size_t)NLAYER * DM   * 2*DI];
__device__ __nv_bfloat16 g_xw_s  [(size_t)NLAYER * 128  * 2*DI];

__device__ __forceinline__ uint32_t s2u(const void* p){
    uint32_t a;
    asm("{ .reg .u64 t; cvta.to.shared.u64 t, %1; cvt.u32.u64 %0, t; }"
        : "=r"(a) : "l"(p));
    return a;
}

// ---------------- embedding gather ----------------------------------------
__global__ void embed_kernel(const int* __restrict__ ids,
                             const float* __restrict__ emb)
{
    int l = blockIdx.x;
    int id = ids[l];
    const float4* src = (const float4*)(emb + (size_t)id * DM);
    float4* dst = (float4*)(g_h + (size_t)l * DM);
    dst[threadIdx.x] = src[threadIdx.x];
}

// ---------------- rmsnorm + fused [h|l] split ------------------------------
__global__ void rmsnorm_split_kernel(const float* __restrict__ in,
                                     __nv_bfloat16* __restrict__ out_s,
                                     const float* __restrict__ w)
{
    int l = blockIdx.x;
    const float* x = in + (size_t)l * DM;
    float ss = 0.f;
    for (int i = threadIdx.x; i < DM; i += 256) {
        float v = x[i];
        ss = fmaf(v, v, ss);
    }
    #pragma unroll
    for (int off = 16; off >= 1; off >>= 1)
        ss += __shfl_xor_sync(0xffffffffu, ss, off);

    __shared__ float red[8];
    __shared__ float scale_s;
    int warp = threadIdx.x >> 5, lane = threadIdx.x & 31;
    if (lane == 0) red[warp] = ss;
    __syncthreads();
    if (threadIdx.x == 0) {
        float t = 0.f;
        #pragma unroll
        for (int i = 0; i < 8; i++) t += red[i];
        scale_s = rsqrtf(t / (float)DM + 1e-5f);
    }
    __syncthreads();
    float scale = scale_s;
    __nv_bfloat16* row = out_s + (size_t)l * 2 * DM;
    for (int i = threadIdx.x; i < DM; i += 256) {
        float v = x[i] * scale * w[i];
        __nv_bfloat16 h = __float2bfloat16(v);
        __nv_bfloat16 lo = __float2bfloat16(v - __bfloat162float(h));
        row[i]      = h;
        row[DM + i] = lo;
    }
}

// ---------------- vectorized [h|l] split -----------------------------------
__device__ __forceinline__ uint32_t pack_bf(__nv_bfloat16 a, __nv_bfloat16 b){
    return (uint32_t)__bfloat16_as_ushort(a) |
           ((uint32_t)__bfloat16_as_ushort(b) << 16);
}

__global__ void split2_kernel(const float* __restrict__ src,
                              __nv_bfloat16* __restrict__ dst,
                              int R, int K, long long total4)
{
    long long idx = (long long)blockIdx.x * blockDim.x + threadIdx.x;
    if (idx >= total4) return;
    int kq = K >> 2;
    int r  = (int)(idx / kq);
    int k4 = (int)(idx - (long long)r * kq);
    float4 v = (r < R) ? ((const float4*)(src + (size_t)r * K))[k4]
                       : make_float4(0.f, 0.f, 0.f, 0.f);
    __nv_bfloat16 h0 = __float2bfloat16(v.x), h1 = __float2bfloat16(v.y);
    __nv_bfloat16 h2 = __float2bfloat16(v.z), h3 = __float2bfloat16(v.w);
    __nv_bfloat16 l0 = __float2bfloat16(v.x - __bfloat162float(h0));
    __nv_bfloat16 l1 = __float2bfloat16(v.y - __bfloat162float(h1));
    __nv_bfloat16 l2 = __float2bfloat16(v.z - __bfloat162float(h2));
    __nv_bfloat16 l3 = __float2bfloat16(v.w - __bfloat162float(h3));
    __nv_bfloat16* row = dst + (size_t)r * 2 * K;
    *(uint2*)(row + 4 * k4)     = make_uint2(pack_bf(h0, h1), pack_bf(h2, h3));
    *(uint2*)(row + K + 4 * k4) = make_uint2(pack_bf(l0, l1), pack_bf(l2, l3));
}

// x_proj weights: all layers, pad 80 -> 128 rows, split [h|l]
__global__ void split2_xw_kernel(const float* __restrict__ xw)
{
    long long idx = (long long)blockIdx.x * blockDim.x + threadIdx.x;
    int kq = DI >> 2;
    int rg = (int)(idx / kq);
    int k4 = (int)(idx - (long long)rg * kq);
    int layer = rg >> 7;
    int r     = rg & 127;
    float4 v = (r < DBL_W)
             ? ((const float4*)(xw + (size_t)layer * DBL_W * DI + (size_t)r * DI))[k4]
             : make_float4(0.f, 0.f, 0.f, 0.f);
    __nv_bfloat16 h0 = __float2bfloat16(v.x), h1 = __float2bfloat16(v.y);
    __nv_bfloat16 h2 = __float2bfloat16(v.z), h3 = __float2bfloat16(v.w);
    __nv_bfloat16 l0 = __float2bfloat16(v.x - __bfloat162float(h0));
    __nv_bfloat16 l1 = __float2bfloat16(v.y - __bfloat162float(h1));
    __nv_bfloat16 l2 = __float2bfloat16(v.z - __bfloat162float(h2));
    __nv_bfloat16 l3 = __float2bfloat16(v.w - __bfloat162float(h3));
    __nv_bfloat16* row = g_xw_s + (size_t)rg * 2 * DI;
    *(uint2*)(row + 4 * k4)      = make_uint2(pack_bf(h0, h1), pack_bf(h2, h3));
    *(uint2*)(row + DI + 4 * k4) = make_uint2(pack_bf(l0, l1), pack_bf(l2, l3));
}

// ---------------- depthwise causal conv + bias + silu + fused xc split -----
__global__ void conv_silu_kernel(const float* __restrict__ cw,
                                 const float* __restrict__ cb)
{
    int idx = blockIdx.x * blockDim.x + threadIdx.x;
    int l = idx / DI;
    int d = idx - l * DI;
    float4 wv = *(const float4*)(cw + (size_t)d * 4);
    float acc = cb[d];
    const float* wj = (const float*)&wv;
    #pragma unroll
    for (int j = 0; j < DCONV; j++) {
        int ll = l - (DCONV - 1) + j;
        if (ll >= 0) acc = fmaf(wj[j], g_xz[(size_t)ll * 2 * DI + d], acc);
    }
    acc = acc / (1.f + __expf(-acc));
    g_xc[idx] = acc;
    __nv_bfloat16 h = __float2bfloat16(acc);
    __nv_bfloat16 lo = __float2bfloat16(acc - __bfloat162float(h));
    __nv_bfloat16* row = g_y_s + (size_t)l * 2 * DI;
    row[d]      = h;
    row[DI + d] = lo;
}

// ---------------- chunked selective scan -----------------------------------
__global__ void scan_pass1_kernel(const float* __restrict__ A_log)
{
    int gw   = threadIdx.x >> 5;
    int lane = threadIdx.x & 31;
    int n    = lane & 15;
    int ch   = (blockIdx.x * 4 + gw) * 2 + (lane >> 4);
    int c    = blockIdx.y;

    float Aval = -__expf(A_log[(size_t)ch * DSTATE + n]);
    float s = 0.f, prod = 1.f;
    int l0 = c * LCHUNK;
    for (int l = l0; l < l0 + LCHUNK; l++) {
        float dtv = g_dt [(size_t)l * DI + ch];
        float xcv = g_xc [(size_t)l * DI + ch];
        float Bv  = g_dbl[(size_t)l * DBL_W + DTRANK + n];
        float dA  = __expf(dtv * Aval);
        s = dA * s + dtv * Bv * xcv;
        prod *= dA;
    }
    int idx = (c * DI + ch) * DSTATE + n;
    g_sc_end[idx]  = s;
    g_sc_prod[idx] = prod;
}

__global__ void scan_fix_kernel()
{
    int i = blockIdx.x * blockDim.x + threadIdx.x;
    float s = 0.f;
    #pragma unroll
    for (int c = 0; c < NCHUNK; c++) {
        g_sc_start[c * DI * DSTATE + i] = s;
        s = g_sc_prod[c * DI * DSTATE + i] * s + g_sc_end[c * DI * DSTATE + i];
    }
}

__global__ void scan_pass2_kernel(const float* __restrict__ A_log)
{
    int gw   = threadIdx.x >> 5;
    int lane = threadIdx.x & 31;
    int n    = lane & 15;
    int ch   = (blockIdx.x * 4 + gw) * 2 + (lane >> 4);
    int c    = blockIdx.y;

    float Aval = -__expf(A_log[(size_t)ch * DSTATE + n]);
    float s = g_sc_start[(c * DI + ch) * DSTATE + n];
    int l0 = c * LCHUNK;
    for (int l = l0; l < l0 + LCHUNK; l++) {
        float dtv = g_dt [(size_t)l * DI + ch];
        float xcv = g_xc [(size_t)l * DI + ch];
        float Bv  = g_dbl[(size_t)l * DBL_W + DTRANK + n];
        float Cv  = g_dbl[(size_t)l * DBL_W + DTRANK + DSTATE + n];
        s = __expf(dtv * Aval) * s + dtv * Bv * xcv;
        float p = s * Cv;
        p += __shfl_xor_sync(0xffffffffu, p, 1);
        p += __shfl_xor_sync(0xffffffffu, p, 2);
        p += __shfl_xor_sync(0xffffffffu, p, 4);
        p += __shfl_xor_sync(0xffffffffu, p, 8);
        if (n == 0) g_y[(size_t)l * DI + ch] = p;
    }
}

// ---------------- y = (y + xc*D) * silu(z), fused [h|l] split --------------
__global__ void y_epi_split_kernel(const float* __restrict__ Dp)
{
    int idx = blockIdx.x * blockDim.x + threadIdx.x;
    int l = idx / DI;
    int d = idx - l * DI;
    float z  = g_xz[(size_t)l * 2 * DI + DI + d];
    float yv = g_y[idx] + g_xc[idx] * Dp[d];
    yv *= z / (1.f + __expf(-z));
    __nv_bfloat16 h = __float2bfloat16(yv);
    __nv_bfloat16 lo = __float2bfloat16(yv - __bfloat162float(h));
    __nv_bfloat16* row = g_y_s + (size_t)l * 2 * DI;
    row[d]      = h;
    row[DI + d] = lo;
}

// ---------------- split-K combines -----------------------------------------
__global__ void combine_h_kernel()
{
    int idx = blockIdx.x * blockDim.x + threadIdx.x;
    const int S = L_SEQ * DM;
    float a = g_part[idx]         + g_part[idx + S]     + g_part[idx + 2 * S];
    float b = g_part[idx + 3 * S] + g_part[idx + 4 * S] + g_part[idx + 5 * S];
    g_h[idx] += a + b;
}

__global__ void combine_dbl_kernel()
{
    int idx = blockIdx.x * blockDim.x + threadIdx.x;
    const int S = L_SEQ * DBL_W;
    float a = 0.f;
    #pragma unroll
    for (int z = 0; z < XPJ_SPLITK; z++) a += g_dblp[z * S + idx];
    g_dbl[idx] = a;
}

// ---------------- fp32 TN GEMM (dt_proj only) ------------------------------
#define GBM 128
#define GBN 64
#define GBK 16

template<int EPI>
__global__ __launch_bounds__(256)
void gemm_tn(const float* __restrict__ A, int lda,
             const float* __restrict__ B, int ldb,
             float* __restrict__ C, int ldc,
             int N, int K, const float* __restrict__ bias)
{
    __shared__ float As[GBK][GBM + 4];
    __shared__ float Bs[GBK][GBN + 4];

    const int bm  = blockIdx.y * GBM;
    const int bn  = blockIdx.x * GBN;
    const int tid = threadIdx.x;
    const int tx  = tid & 15;
    const int ty  = tid >> 4;
    const int a_row = tid >> 1;
    const int a_k   = (tid & 1) * 8;
    const int b_row = tid >> 2;
    const int b_k   = (tid & 3) * 4;

    float acc[8][4];
    #pragma unroll
    for (int i = 0; i < 8; i++)
        #pragma unroll
        for (int j = 0; j < 4; j++) acc[i][j] = 0.f;

    const float* Aptr = A + (size_t)(bm + a_row) * lda + a_k;
    const int gbn = bn + b_row;
    const float* Bptr = (gbn < N) ? (B + (size_t)gbn * ldb + b_k) : 0;

    for (int k0 = 0; k0 < K; k0 += GBK) {
        float4 av0 = *(const float4*)(Aptr + k0);
        float4 av1 = *(const float4*)(Aptr + k0 + 4);
        float4 bv  = Bptr ? *(const float4*)(Bptr + k0)
                          : make_float4(0.f, 0.f, 0.f, 0.f);

        As[a_k + 0][a_row] = av0.x; As[a_k + 1][a_row] = av0.y;
        As[a_k + 2][a_row] = av0.z; As[a_k + 3][a_row] = av0.w;
        As[a_k + 4][a_row] = av1.x; As[a_k + 5][a_row] = av1.y;
        As[a_k + 6][a_row] = av1.z; As[a_k + 7][a_row] = av1.w;
        Bs[b_k + 0][b_row] = bv.x;  Bs[b_k + 1][b_row] = bv.y;
        Bs[b_k + 2][b_row] = bv.z;  Bs[b_k + 3][b_row] = bv.w;
        __syncthreads();

        #pragma unroll
        for (int kk = 0; kk < GBK; kk++) {
            float ar[8], br[4];
            #pragma unroll
            for (int i = 0; i < 8; i++) ar[i] = As[kk][ty * 8 + i];
            #pragma unroll
            for (int j = 0; j < 4; j++) br[j] = Bs[kk][tx * 4 + j];
            #pragma unroll
            for (int i = 0; i < 8; i++)
                #pragma unroll
                for (int j = 0; j < 4; j++)
                    acc[i][j] = fmaf(ar[i], br[j], acc[i][j]);
        }
        __syncthreads();
    }

    #pragma unroll
    for (int i = 0; i < 8; i++) {
        int m = bm + ty * 8 + i;
        #pragma unroll
        for (int j = 0; j < 4; j++) {
            int n = bn + tx * 4 + j;
            if (n < N) {
                float v = acc[i][j];
                if (EPI == 1) {
                    v += bias[n];
                    v = fmaxf(v, 0.f) + log1pf(__expf(-fabsf(v)));
                }
                C[(size_t)m * ldc + n] = v;
            }
        }
    }
}

// ---------------- bf16 HMMA GEMM, templated N tile, 4-stage pair loop ------
#define TCM 128
#define TCK 32

__device__ __forceinline__ void cp_async16(uint32_t s, const void* g)
{
    asm volatile("cp.async.cg.shared.global [%0], [%1], 16;\n"
                 :: "r"(s), "l"(g));
}
__device__ __forceinline__ void cp_commit(){ asm volatile("cp.async.commit_group;\n" ::: "memory"); }
template<int N> __device__ __forceinline__ void cp_wait(){ asm volatile("cp.async.wait_group %0;\n" :: "n"(N) : "memory"); }

__device__ __forceinline__ void ldsm_x4(uint32_t* r, uint32_t addr)
{
    asm volatile("ldmatrix.sync.aligned.m8n8.x4.shared.b16 {%0,%1,%2,%3}, [%4];"
                 : "=r"(r[0]), "=r"(r[1]), "=r"(r[2]), "=r"(r[3]) : "r"(addr));
}
__device__ __forceinline__ void mma16816(float* c, const uint32_t* a, const uint32_t* b)
{
    asm volatile(
        "mma.sync.aligned.m16n8k16.row.col.f32.bf16.bf16.f32 "
        "{%0,%1,%2,%3}, {%4,%5,%6,%7}, {%8,%9}, {%0,%1,%2,%3};"
        : "+f"(c[0]), "+f"(c[1]), "+f"(c[2]), "+f"(c[3])
        : "r"(a[0]), "r"(a[1]), "r"(a[2]), "r"(a[3]), "r"(b[0]), "r"(b[1]));
}

__device__ __forceinline__ uint32_t swz(int row, int chunk){
    return (uint32_t)(row * 64 + ((chunk ^ ((row >> 1) & 3)) * 16));
}

template<int TN>
__global__ __launch_bounds__(TN == 64 ? 128 : 256, TN == 64 ? 4 : 2)
void mma_gemm(const __nv_bfloat16* __restrict__ A,
              const __nv_bfloat16* __restrict__ B,
              float* __restrict__ C, int ldc, int N, int Kreal,
              int cps, long long partStride)
{
    constexpr int NT   = (TN == 64) ? 128 : 256;
    constexpr int ASZ  = TCM * 64;
    constexpr int BSZ  = TN * 64;
    constexpr int STG  = ASZ + BSZ;
    constexpr int AI   = (TCM * 4) / NT;
    constexpr int BI   = (TN * 4) / NT;

    extern __shared__ __align__(16) char sm[];
    const uint32_t sbase = s2u(sm);
    const int tid  = threadIdx.x;
    const int wid  = tid >> 5, lane = tid & 31;
    const int wm   = wid & 1;
    const int wn   = wid >> 1;
    const int bm   = blockIdx.x * TCM;
    const int bn   = blockIdx.y * TN;
    const int KC   = Kreal / TCK;
    const int c0   = blockIdx.z * cps;
    const int c1   = c0 + cps;
    C += (long long)blockIdx.z * partStride;

    const int lda = 2 * Kreal;

    const __nv_bfloat16* Ag[AI]; uint32_t sa[AI];
    #pragma unroll
    for (int i = 0; i < AI; i++) {
        int v = tid + i * NT, r = v >> 2, k8 = v & 3;
        Ag[i] = A + (size_t)(bm + r) * lda + k8 * 8;
        sa[i] = sbase + swz(r, k8);
    }
    const __nv_bfloat16* Bg[BI]; uint32_t sb[BI];
    #pragma unroll
    for (int i = 0; i < BI; i++) {
        int v = tid + i * NT, r = v >> 2, k8 = v & 3;
        Bg[i] = B + (size_t)(bn + r) * lda + k8 * 8;
        sb[i] = sbase + ASZ + swz(r, k8);
    }

    float acc[4][4][4];
    #pragma unroll
    for (int i = 0; i < 4; i++)
        #pragma unroll
        for (int j = 0; j < 4; j++)
            #pragma unroll
            for (int t = 0; t < 4; t++) acc[i][j][t] = 0.f;

    const int a_row = wm * 64 + (lane & 15);
    const int a_k8s = lane >> 4;
    const int b_row = wn * 32 + (lane & 7) + ((lane >> 4) << 3);
    const int b_k8s = (lane >> 3) & 1;

    #define LOAD_STAGE(cc) do { \
        uint32_t so = (uint32_t)(((cc) - c0) & 3) * STG; \
        int ac = ((cc) < 2*KC ? (cc) : (cc) - 2*KC) * TCK; \
        int bc = ((cc) < KC   ? (cc) : (cc) - KC)   * TCK; \
        _Pragma("unroll") \
        for (int i = 0; i < AI; i++) cp_async16(sa[i] + so, Ag[i] + ac); \
        _Pragma("unroll") \
        for (int i = 0; i < BI; i++) cp_async16(sb[i] + so, Bg[i] + bc); \
        cp_commit(); \
    } while (0)

    #define MATH_STAGE(cc) do { \
        const uint32_t sA = sbase + (uint32_t)(((cc) - c0) & 3) * STG; \
        const uint32_t sB = sA + ASZ; \
        _Pragma("unroll") \
        for (int k16 = 0; k16 < 2; k16++) { \
            uint32_t afrag[4][4]; \
            _Pragma("unroll") \
            for (int mt = 0; mt < 4; mt++) { \
                int row = a_row + mt * 16; \
                ldsm_x4(afrag[mt], sA + swz(row, k16 * 2 + a_k8s)); \
            } \
            uint32_t bfrag[4][2]; \
            _Pragma("unroll") \
            for (int np = 0; np < 2; np++) { \
                int row = b_row + np * 16; \
                uint32_t t[4]; \
                ldsm_x4(t, sB + swz(row, k16 * 2 + b_k8s)); \
                bfrag[np * 2 + 0][0] = t[0]; bfrag[np * 2 + 0][1] = t[1]; \
                bfrag[np * 2 + 1][0] = t[2]; bfrag[np * 2 + 1][1] = t[3]; \
            } \
            _Pragma("unroll") \
            for (int mt = 0; mt < 4; mt++) \
                _Pragma("unroll") \
                for (int nt = 0; nt < 4; nt++) \
                    mma16816(acc[mt][nt], afrag[mt], bfrag[nt]); \
        } \
    } while (0)

    LOAD_STAGE(c0);
    if (c1 - c0 > 1) LOAD_STAGE(c0 + 1);

    for (int c = c0; c < c1; c += 2) {
        cp_wait<0>();
        __syncthreads();
        if (c + 2 < c1) { LOAD_STAGE(c + 2); LOAD_STAGE(c + 3); }
        MATH_STAGE(c);
        MATH_STAGE(c + 1);
    }
    #undef LOAD_STAGE
    #undef MATH_STAGE

    const int erow = lane >> 2;
    const int ecol = (lane & 3) * 2;
    #pragma unroll
    for (int mt = 0; mt < 4; mt++) {
        #pragma unroll
        for (int nt = 0; nt < 4; nt++) {
            int m0 = bm + wm * 64 + mt * 16 + erow;
            int n0 = bn + wn * 32 + nt * 8 + ecol;
            if (n0 < N) {
                float* p0 = C + (size_t)m0 * ldc + n0;
                float* p1 = p0 + 8 * ldc;
                *(float2*)p0 = make_float2(acc[mt][nt][0], acc[mt][nt][1]);
                *(float2*)p1 = make_float2(acc[mt][nt][2], acc[mt][nt][3]);
            }
        }
    }
}

#define SMEM64  (4 * (TCM*64 + 64*64))    // 49152
#define SMEM128 (4 * (TCM*64 + 128*64))   // 65536

// ---------------- orchestration --------------------------------------------
extern "C" void kernel_launch(void* const* d_in, const int* in_sizes, int n_in,
                              void* d_out, int out_size)
{
    const int*   ids        = (const int*)  d_in[0];
    const float* emb        = (const float*)d_in[1];
    const float* in_proj_w  = (const float*)d_in[2];
    const float* conv_w     = (const float*)d_in[3];
    const float* conv_b     = (const float*)d_in[4];
    const float* x_proj_w   = (const float*)d_in[5];
    const float* dt_proj_w  = (const float*)d_in[6];
    const float* dt_proj_b  = (const float*)d_in[7];
    const float* A_log      = (const float*)d_in[8];
    const float* D_param    = (const float*)d_in[9];
    const float* out_proj_w = (const float*)d_in[10];
    const float* norm_w     = (const float*)d_in[11];
    const float* norm_f_w   = (const float*)d_in[12];
    float* logits = (float*)d_out;

    cudaFuncSetAttribute(mma_gemm<64>,
                         cudaFuncAttributeMaxDynamicSharedMemorySize, SMEM64);
    cudaFuncSetAttribute(mma_gemm<128>,
                         cudaFuncAttributeMaxDynamicSharedMemorySize, SMEM128);

    float *h, *xz, *xc, *dbl, *dblp, *dt, *y, *part;
    cudaGetSymbolAddress((void**)&h,    g_h);
    cudaGetSymbolAddress((void**)&xz,   g_xz);
    cudaGetSymbolAddress((void**)&xc,   g_xc);
    cudaGetSymbolAddress((void**)&dbl,  g_dbl);
    cudaGetSymbolAddress((void**)&dblp, g_dblp);
    cudaGetSymbolAddress((void**)&dt,   g_dt);
    cudaGetSymbolAddress((void**)&y,    g_y);
    cudaGetSymbolAddress((void**)&part, g_part);

    __nv_bfloat16 *emb_s, *hn_s, *inw_s, *y_s, *outw_s, *xw_s;
    cudaGetSymbolAddress((void**)&emb_s,  g_emb_s);
    cudaGetSymbolAddress((void**)&hn_s,   g_hn_s);
    cudaGetSymbolAddress((void**)&inw_s,  g_inw_s);
    cudaGetSymbolAddress((void**)&y_s,    g_y_s);
    cudaGetSymbolAddress((void**)&outw_s, g_outw_s);
    cudaGetSymbolAddress((void**)&xw_s,   g_xw_s);

    embed_kernel<<<L_SEQ, DM / 4>>>(ids, emb);

    // ---- batched weight/embedding splits (hoisted out of the layer loop) --
    {
        long long t1 = (long long)NLAYER * 2 * DI * DM / 4;
        split2_kernel<<<(unsigned)((t1 + 255) / 256), 256>>>(
            in_proj_w, inw_s, NLAYER * 2 * DI, DM, t1);

        long long t2 = (long long)NLAYER * DM * DI / 4;
        split2_kernel<<<(unsigned)((t2 + 255) / 256), 256>>>(
            out_proj_w, outw_s, NLAYER * DM, DI, t2);

        long long t3 = (long long)NLAYER * 128 * DI / 4;
        split2_xw_kernel<<<(unsigned)((t3 + 255) / 256), 256>>>(x_proj_w);

        long long t4 = (long long)VOCAB_PAD * DM / 4;
        split2_kernel<<<(unsigned)((t4 + 255) / 256), 256>>>(
            emb, emb_s, VOCAB, DM, t4);
    }

    for (int i = 0; i < NLAYER; i++) {
        rmsnorm_split_kernel<<<L_SEQ, 256>>>(h, hn_s, norm_w + (size_t)i * DM);

        // xz = hn @ in_proj_w^T   (1024 x 3072, K=768)
        {
            dim3 g1(L_SEQ / TCM, 2 * DI / 64, 1);
            mma_gemm<64><<<g1, 128, SMEM64>>>(
                hn_s, inw_s + (size_t)i * 2 * DI * 2 * DM,
                xz, 2 * DI, 2 * DI, DM, 3 * (DM / TCK), 0);
        }

        conv_silu_kernel<<<(L_SEQ * DI) / 256, 256>>>(
            conv_w + (size_t)i * DI * DCONV, conv_b + (size_t)i * DI);

        // dbl = xc @ x_proj_w^T   (split-K=9, cps=16)
        {
            dim3 g2(L_SEQ / TCM, 2, XPJ_SPLITK);
            mma_gemm<64><<<g2, 128, SMEM64>>>(
                y_s, xw_s + (size_t)i * 128 * 2 * DI,
                dblp, DBL_W, DBL_W, DI,
                3 * (DI / TCK) / XPJ_SPLITK, (long long)L_SEQ * DBL_W);
        }
        combine_dbl_kernel<<<(L_SEQ * DBL_W) / 256, 256>>>();

        // dt = softplus(dbl[:, :48] @ dt_proj_w^T + b)
        {
            dim3 g3((DI + GBN - 1) / GBN, L_SEQ / GBM);
            gemm_tn<1><<<g3, 256>>>(dbl, DBL_W,
                                    dt_proj_w + (size_t)i * DI * DTRANK, DTRANK,
                                    dt, DI, DI, DTRANK,
                                    dt_proj_b + (size_t)i * DI);
        }

        // chunked selective scan
        {
            const float* Al = A_log + (size_t)i * DI * DSTATE;
            dim3 gs(DI / 8, NCHUNK);
            scan_pass1_kernel<<<gs, 128>>>(Al);
            scan_fix_kernel<<<(DI * DSTATE) / 256, 256>>>();
            scan_pass2_kernel<<<gs, 128>>>(Al);
        }

        y_epi_split_kernel<<<(L_SEQ * DI) / 256, 256>>>(D_param + (size_t)i * DI);

        // part[z] = y @ out_proj_w^T, split-K=6 (cps=24)
        {
            dim3 g4(L_SEQ / TCM, DM / 64, 6);
            mma_gemm<64><<<g4, 128, SMEM64>>>(
                y_s, outw_s + (size_t)i * DM * 2 * DI,
                part, DM, DM, DI,
                3 * (DI / TCK) / 6, (long long)L_SEQ * DM);
        }
        combine_h_kernel<<<(L_SEQ * DM) / 256, 256>>>();
    }

    rmsnorm_split_kernel<<<L_SEQ, 256>>>(h, hn_s, norm_f_w);

    // logits = hn @ emb^T — TN=128 tile
    {
        dim3 g5(L_SEQ / TCM, VOCAB_PAD / 128, 1);
        mma_gemm<128><<<g5, 256, SMEM128>>>(hn_s, emb_s, logits, VOCAB, VOCAB, DM,
                                            3 * (DM / TCK), 0);
    }
}

// round 15
// speedup vs baseline: 1.4469x; 1.3654x over previous
#include <cuda_runtime.h>
#include <cuda_bf16.h>
#include <cuda_fp16.h>
#include <math.h>
#include <stdint.h>

#define L_SEQ 1024
#define DM 768
#define DI 1536
#define DSTATE 16
#define DCONV 4
#define DTRANK 48
#define NLAYER 4
#define VOCAB 50280
#define VOCAB_PAD 50304            // 393*128
#define DBL_W (DTRANK + 2*DSTATE)  // 80
#define NCHUNK 16
#define LCHUNK (L_SEQ / NCHUNK)    // 64
#define XPJ_SPLITK 9

// ---------------- scratch (device globals) ---------------------------------
__device__ float g_h [L_SEQ*DM];
__device__ float g_xz[L_SEQ*2*DI];
__device__ float g_xc[L_SEQ*DI];
__device__ float g_dbl[L_SEQ*DBL_W];
__device__ float g_dblp[XPJ_SPLITK * L_SEQ * DBL_W];
__device__ float g_dt[L_SEQ*DI];
__device__ float g_y [L_SEQ*DI];
__device__ float g_part[6 * L_SEQ * DM];

// chunked-scan state buffers
__device__ float g_sc_end [NCHUNK*DI*DSTATE];
__device__ float g_sc_prod[NCHUNK*DI*DSTATE];
__device__ float g_sc_start[NCHUNK*DI*DSTATE];

// bf16 2-segment split buffers (layer GEMMs): row = [hi | lo], width 2K.
__device__ __nv_bfloat16 g_hn_s  [(size_t)L_SEQ * 2 * DM];
__device__ __nv_bfloat16 g_y_s   [(size_t)L_SEQ * 2 * DI];
__device__ __nv_bfloat16 g_inw_s [(size_t)NLAYER * 2*DI * 2*DM];
__device__ __nv_bfloat16 g_outw_s[(size_t)NLAYER * DM   * 2*DI];
__device__ __nv_bfloat16 g_xw_s  [(size_t)NLAYER * 128  * 2*DI];

// fp16 single-segment buffers (logits GEMM only)
__device__ __half g_emb_h[(size_t)VOCAB_PAD * DM];
__device__ __half g_hn_h [(size_t)L_SEQ * DM];

__device__ __forceinline__ uint32_t s2u(const void* p){
    uint32_t a;
    asm("{ .reg .u64 t; cvta.to.shared.u64 t, %1; cvt.u32.u64 %0, t; }"
        : "=r"(a) : "l"(p));
    return a;
}

// ---------------- embedding gather ----------------------------------------
__global__ void embed_kernel(const int* __restrict__ ids,
                             const float* __restrict__ emb)
{
    int l = blockIdx.x;
    int id = ids[l];
    const float4* src = (const float4*)(emb + (size_t)id * DM);
    float4* dst = (float4*)(g_h + (size_t)l * DM);
    dst[threadIdx.x] = src[threadIdx.x];
}

// ---------------- rmsnorm + fused bf16 [h|l] split (layer path) ------------
__global__ void rmsnorm_split_kernel(const float* __restrict__ in,
                                     __nv_bfloat16* __restrict__ out_s,
                                     const float* __restrict__ w)
{
    int l = blockIdx.x;
    const float* x = in + (size_t)l * DM;
    float ss = 0.f;
    for (int i = threadIdx.x; i < DM; i += 256) {
        float v = x[i];
        ss = fmaf(v, v, ss);
    }
    #pragma unroll
    for (int off = 16; off >= 1; off >>= 1)
        ss += __shfl_xor_sync(0xffffffffu, ss, off);

    __shared__ float red[8];
    __shared__ float scale_s;
    int warp = threadIdx.x >> 5, lane = threadIdx.x & 31;
    if (lane == 0) red[warp] = ss;
    __syncthreads();
    if (threadIdx.x == 0) {
        float t = 0.f;
        #pragma unroll
        for (int i = 0; i < 8; i++) t += red[i];
        scale_s = rsqrtf(t / (float)DM + 1e-5f);
    }
    __syncthreads();
    float scale = scale_s;
    __nv_bfloat16* row = out_s + (size_t)l * 2 * DM;
    for (int i = threadIdx.x; i < DM; i += 256) {
        float v = x[i] * scale * w[i];
        __nv_bfloat16 h = __float2bfloat16(v);
        __nv_bfloat16 lo = __float2bfloat16(v - __bfloat162float(h));
        row[i]      = h;
        row[DM + i] = lo;
    }
}

// ---------------- final rmsnorm -> fp16 (logits path) ----------------------
__global__ void rmsnorm_f16_kernel(const float* __restrict__ in,
                                   const float* __restrict__ w)
{
    int l = blockIdx.x;
    const float* x = in + (size_t)l * DM;
    float ss = 0.f;
    for (int i = threadIdx.x; i < DM; i += 256) {
        float v = x[i];
        ss = fmaf(v, v, ss);
    }
    #pragma unroll
    for (int off = 16; off >= 1; off >>= 1)
        ss += __shfl_xor_sync(0xffffffffu, ss, off);

    __shared__ float red[8];
    __shared__ float scale_s;
    int warp = threadIdx.x >> 5, lane = threadIdx.x & 31;
    if (lane == 0) red[warp] = ss;
    __syncthreads();
    if (threadIdx.x == 0) {
        float t = 0.f;
        #pragma unroll
        for (int i = 0; i < 8; i++) t += red[i];
        scale_s = rsqrtf(t / (float)DM + 1e-5f);
    }
    __syncthreads();
    float scale = scale_s;
    __half* row = g_hn_h + (size_t)l * DM;
    for (int i = threadIdx.x; i < DM; i += 256)
        row[i] = __float2half(x[i] * scale * w[i]);
}

// ---------------- vectorized bf16 [h|l] split ------------------------------
__device__ __forceinline__ uint32_t pack_bf(__nv_bfloat16 a, __nv_bfloat16 b){
    return (uint32_t)__bfloat16_as_ushort(a) |
           ((uint32_t)__bfloat16_as_ushort(b) << 16);
}

__global__ void split2_kernel(const float* __restrict__ src,
                              __nv_bfloat16* __restrict__ dst,
                              int R, int K, long long total4)
{
    long long idx = (long long)blockIdx.x * blockDim.x + threadIdx.x;
    if (idx >= total4) return;
    int kq = K >> 2;
    int r  = (int)(idx / kq);
    int k4 = (int)(idx - (long long)r * kq);
    float4 v = (r < R) ? ((const float4*)(src + (size_t)r * K))[k4]
                       : make_float4(0.f, 0.f, 0.f, 0.f);
    __nv_bfloat16 h0 = __float2bfloat16(v.x), h1 = __float2bfloat16(v.y);
    __nv_bfloat16 h2 = __float2bfloat16(v.z), h3 = __float2bfloat16(v.w);
    __nv_bfloat16 l0 = __float2bfloat16(v.x - __bfloat162float(h0));
    __nv_bfloat16 l1 = __float2bfloat16(v.y - __bfloat162float(h1));
    __nv_bfloat16 l2 = __float2bfloat16(v.z - __bfloat162float(h2));
    __nv_bfloat16 l3 = __float2bfloat16(v.w - __bfloat162float(h3));
    __nv_bfloat16* row = dst + (size_t)r * 2 * K;
    *(uint2*)(row + 4 * k4)     = make_uint2(pack_bf(h0, h1), pack_bf(h2, h3));
    *(uint2*)(row + K + 4 * k4) = make_uint2(pack_bf(l0, l1), pack_bf(l2, l3));
}

// x_proj weights: all layers, pad 80 -> 128 rows, split [h|l]
__global__ void split2_xw_kernel(const float* __restrict__ xw)
{
    long long idx = (long long)blockIdx.x * blockDim.x + threadIdx.x;
    int kq = DI >> 2;
    int rg = (int)(idx / kq);
    int k4 = (int)(idx - (long long)rg * kq);
    int layer = rg >> 7;
    int r     = rg & 127;
    float4 v = (r < DBL_W)
             ? ((const float4*)(xw + (size_t)layer * DBL_W * DI + (size_t)r * DI))[k4]
             : make_float4(0.f, 0.f, 0.f, 0.f);
    __nv_bfloat16 h0 = __float2bfloat16(v.x), h1 = __float2bfloat16(v.y);
    __nv_bfloat16 h2 = __float2bfloat16(v.z), h3 = __float2bfloat16(v.w);
    __nv_bfloat16 l0 = __float2bfloat16(v.x - __bfloat162float(h0));
    __nv_bfloat16 l1 = __float2bfloat16(v.y - __bfloat162float(h1));
    __nv_bfloat16 l2 = __float2bfloat16(v.z - __bfloat162float(h2));
    __nv_bfloat16 l3 = __float2bfloat16(v.w - __bfloat162float(h3));
    __nv_bfloat16* row = g_xw_s + (size_t)rg * 2 * DI;
    *(uint2*)(row + 4 * k4)      = make_uint2(pack_bf(h0, h1), pack_bf(h2, h3));
    *(uint2*)(row + DI + 4 * k4) = make_uint2(pack_bf(l0, l1), pack_bf(l2, l3));
}

// embedding -> fp16 (dense, zero-pad rows >= VOCAB)
__global__ void tofp16_kernel(const float* __restrict__ src,
                              __half* __restrict__ dst,
                              int R, int K, long long total4)
{
    long long idx = (long long)blockIdx.x * blockDim.x + threadIdx.x;
    if (idx >= total4) return;
    int kq = K >> 2;
    int r  = (int)(idx / kq);
    float4 v = (r < R) ? ((const float4*)src)[idx]
                       : make_float4(0.f, 0.f, 0.f, 0.f);
    __half2 a = __floats2half2_rn(v.x, v.y);
    __half2 b = __floats2half2_rn(v.z, v.w);
    *(uint2*)(dst + idx * 4) = make_uint2(*(uint32_t*)&a, *(uint32_t*)&b);
}

// ---------------- depthwise causal conv + bias + silu + fused xc split -----
__global__ void conv_silu_kernel(const float* __restrict__ cw,
                                 const float* __restrict__ cb)
{
    int idx = blockIdx.x * blockDim.x + threadIdx.x;
    int l = idx / DI;
    int d = idx - l * DI;
    float4 wv = *(const float4*)(cw + (size_t)d * 4);
    float acc = cb[d];
    const float* wj = (const float*)&wv;
    #pragma unroll
    for (int j = 0; j < DCONV; j++) {
        int ll = l - (DCONV - 1) + j;
        if (ll >= 0) acc = fmaf(wj[j], g_xz[(size_t)ll * 2 * DI + d], acc);
    }
    acc = acc / (1.f + __expf(-acc));
    g_xc[idx] = acc;
    __nv_bfloat16 h = __float2bfloat16(acc);
    __nv_bfloat16 lo = __float2bfloat16(acc - __bfloat162float(h));
    __nv_bfloat16* row = g_y_s + (size_t)l * 2 * DI;
    row[d]      = h;
    row[DI + d] = lo;
}

// ---------------- chunked selective scan -----------------------------------
__global__ void scan_pass1_kernel(const float* __restrict__ A_log)
{
    int gw   = threadIdx.x >> 5;
    int lane = threadIdx.x & 31;
    int n    = lane & 15;
    int ch   = (blockIdx.x * 4 + gw) * 2 + (lane >> 4);
    int c    = blockIdx.y;

    float Aval = -__expf(A_log[(size_t)ch * DSTATE + n]);
    float s = 0.f, prod = 1.f;
    int l0 = c * LCHUNK;
    for (int l = l0; l < l0 + LCHUNK; l++) {
        float dtv = g_dt [(size_t)l * DI + ch];
        float xcv = g_xc [(size_t)l * DI + ch];
        float Bv  = g_dbl[(size_t)l * DBL_W + DTRANK + n];
        float dA  = __expf(dtv * Aval);
        s = dA * s + dtv * Bv * xcv;
        prod *= dA;
    }
    int idx = (c * DI + ch) * DSTATE + n;
    g_sc_end[idx]  = s;
    g_sc_prod[idx] = prod;
}

__global__ void scan_fix_kernel()
{
    int i = blockIdx.x * blockDim.x + threadIdx.x;
    float s = 0.f;
    #pragma unroll
    for (int c = 0; c < NCHUNK; c++) {
        g_sc_start[c * DI * DSTATE + i] = s;
        s = g_sc_prod[c * DI * DSTATE + i] * s + g_sc_end[c * DI * DSTATE + i];
    }
}

__global__ void scan_pass2_kernel(const float* __restrict__ A_log)
{
    int gw   = threadIdx.x >> 5;
    int lane = threadIdx.x & 31;
    int n    = lane & 15;
    int ch   = (blockIdx.x * 4 + gw) * 2 + (lane >> 4);
    int c    = blockIdx.y;

    float Aval = -__expf(A_log[(size_t)ch * DSTATE + n]);
    float s = g_sc_start[(c * DI + ch) * DSTATE + n];
    int l0 = c * LCHUNK;
    for (int l = l0; l < l0 + LCHUNK; l++) {
        float dtv = g_dt [(size_t)l * DI + ch];
        float xcv = g_xc [(size_t)l * DI + ch];
        float Bv  = g_dbl[(size_t)l * DBL_W + DTRANK + n];
        float Cv  = g_dbl[(size_t)l * DBL_W + DTRANK + DSTATE + n];
        s = __expf(dtv * Aval) * s + dtv * Bv * xcv;
        float p = s * Cv;
        p += __shfl_xor_sync(0xffffffffu, p, 1);
        p += __shfl_xor_sync(0xffffffffu, p, 2);
        p += __shfl_xor_sync(0xffffffffu, p, 4);
        p += __shfl_xor_sync(0xffffffffu, p, 8);
        if (n == 0) g_y[(size_t)l * DI + ch] = p;
    }
}

// ---------------- y = (y + xc*D) * silu(z), fused bf16 split ---------------
__global__ void y_epi_split_kernel(const float* __restrict__ Dp)
{
    int idx = blockIdx.x * blockDim.x + threadIdx.x;
    int l = idx / DI;
    int d = idx - l * DI;
    float z  = g_xz[(size_t)l * 2 * DI + DI + d];
    float yv = g_y[idx] + g_xc[idx] * Dp[d];
    yv *= z / (1.f + __expf(-z));
    __nv_bfloat16 h = __float2bfloat16(yv);
    __nv_bfloat16 lo = __float2bfloat16(yv - __bfloat162float(h));
    __nv_bfloat16* row = g_y_s + (size_t)l * 2 * DI;
    row[d]      = h;
    row[DI + d] = lo;
}

// ---------------- split-K combines -----------------------------------------
__global__ void combine_h_kernel()
{
    int idx = blockIdx.x * blockDim.x + threadIdx.x;
    const int S = L_SEQ * DM;
    float a = g_part[idx]         + g_part[idx + S]     + g_part[idx + 2 * S];
    float b = g_part[idx + 3 * S] + g_part[idx + 4 * S] + g_part[idx + 5 * S];
    g_h[idx] += a + b;
}

__global__ void combine_dbl_kernel()
{
    int idx = blockIdx.x * blockDim.x + threadIdx.x;
    const int S = L_SEQ * DBL_W;
    float a = 0.f;
    #pragma unroll
    for (int z = 0; z < XPJ_SPLITK; z++) a += g_dblp[z * S + idx];
    g_dbl[idx] = a;
}

// ---------------- fp32 TN GEMM (dt_proj only) ------------------------------
#define GBM 128
#define GBN 64
#define GBK 16

template<int EPI>
__global__ __launch_bounds__(256)
void gemm_tn(const float* __restrict__ A, int lda,
             const float* __restrict__ B, int ldb,
             float* __restrict__ C, int ldc,
             int N, int K, const float* __restrict__ bias)
{
    __shared__ float As[GBK][GBM + 4];
    __shared__ float Bs[GBK][GBN + 4];

    const int bm  = blockIdx.y * GBM;
    const int bn  = blockIdx.x * GBN;
    const int tid = threadIdx.x;
    const int tx  = tid & 15;
    const int ty  = tid >> 4;
    const int a_row = tid >> 1;
    const int a_k   = (tid & 1) * 8;
    const int b_row = tid >> 2;
    const int b_k   = (tid & 3) * 4;

    float acc[8][4];
    #pragma unroll
    for (int i = 0; i < 8; i++)
        #pragma unroll
        for (int j = 0; j < 4; j++) acc[i][j] = 0.f;

    const float* Aptr = A + (size_t)(bm + a_row) * lda + a_k;
    const int gbn = bn + b_row;
    const float* Bptr = (gbn < N) ? (B + (size_t)gbn * ldb + b_k) : 0;

    for (int k0 = 0; k0 < K; k0 += GBK) {
        float4 av0 = *(const float4*)(Aptr + k0);
        float4 av1 = *(const float4*)(Aptr + k0 + 4);
        float4 bv  = Bptr ? *(const float4*)(Bptr + k0)
                          : make_float4(0.f, 0.f, 0.f, 0.f);

        As[a_k + 0][a_row] = av0.x; As[a_k + 1][a_row] = av0.y;
        As[a_k + 2][a_row] = av0.z; As[a_k + 3][a_row] = av0.w;
        As[a_k + 4][a_row] = av1.x; As[a_k + 5][a_row] = av1.y;
        As[a_k + 6][a_row] = av1.z; As[a_k + 7][a_row] = av1.w;
        Bs[b_k + 0][b_row] = bv.x;  Bs[b_k + 1][b_row] = bv.y;
        Bs[b_k + 2][b_row] = bv.z;  Bs[b_k + 3][b_row] = bv.w;
        __syncthreads();

        #pragma unroll
        for (int kk = 0; kk < GBK; kk++) {
            float ar[8], br[4];
            #pragma unroll
            for (int i = 0; i < 8; i++) ar[i] = As[kk][ty * 8 + i];
            #pragma unroll
            for (int j = 0; j < 4; j++) br[j] = Bs[kk][tx * 4 + j];
            #pragma unroll
            for (int i = 0; i < 8; i++)
                #pragma unroll
                for (int j = 0; j < 4; j++)
                    acc[i][j] = fmaf(ar[i], br[j], acc[i][j]);
        }
        __syncthreads();
    }

    #pragma unroll
    for (int i = 0; i < 8; i++) {
        int m = bm + ty * 8 + i;
        #pragma unroll
        for (int j = 0; j < 4; j++) {
            int n = bn + tx * 4 + j;
            if (n < N) {
                float v = acc[i][j];
                if (EPI == 1) {
                    v += bias[n];
                    v = fmaxf(v, 0.f) + log1pf(__expf(-fabsf(v)));
                }
                C[(size_t)m * ldc + n] = v;
            }
        }
    }
}

// ---------------- tensor-core GEMM common helpers --------------------------
#define TCM 128
#define TCK 32

__device__ __forceinline__ void cp_async16(uint32_t s, const void* g)
{
    asm volatile("cp.async.cg.shared.global [%0], [%1], 16;\n"
                 :: "r"(s), "l"(g));
}
__device__ __forceinline__ void cp_commit(){ asm volatile("cp.async.commit_group;\n" ::: "memory"); }
template<int N> __device__ __forceinline__ void cp_wait(){ asm volatile("cp.async.wait_group %0;\n" :: "n"(N) : "memory"); }

__device__ __forceinline__ void ldsm_x4(uint32_t* r, uint32_t addr)
{
    asm volatile("ldmatrix.sync.aligned.m8n8.x4.shared.b16 {%0,%1,%2,%3}, [%4];"
                 : "=r"(r[0]), "=r"(r[1]), "=r"(r[2]), "=r"(r[3]) : "r"(addr));
}
__device__ __forceinline__ void mma16816(float* c, const uint32_t* a, const uint32_t* b)
{
    asm volatile(
        "mma.sync.aligned.m16n8k16.row.col.f32.bf16.bf16.f32 "
        "{%0,%1,%2,%3}, {%4,%5,%6,%7}, {%8,%9}, {%0,%1,%2,%3};"
        : "+f"(c[0]), "+f"(c[1]), "+f"(c[2]), "+f"(c[3])
        : "r"(a[0]), "r"(a[1]), "r"(a[2]), "r"(a[3]), "r"(b[0]), "r"(b[1]));
}
__device__ __forceinline__ void mma16816h(float* c, const uint32_t* a, const uint32_t* b)
{
    asm volatile(
        "mma.sync.aligned.m16n8k16.row.col.f32.f16.f16.f32 "
        "{%0,%1,%2,%3}, {%4,%5,%6,%7}, {%8,%9}, {%0,%1,%2,%3};"
        : "+f"(c[0]), "+f"(c[1]), "+f"(c[2]), "+f"(c[3])
        : "r"(a[0]), "r"(a[1]), "r"(a[2]), "r"(a[3]), "r"(b[0]), "r"(b[1]));
}

__device__ __forceinline__ uint32_t swz(int row, int chunk){
    return (uint32_t)(row * 64 + ((chunk ^ ((row >> 1) & 3)) * 16));
}

// ---------------- bf16x3 HMMA GEMM (layer GEMMs), 4-stage pair loop --------
template<int TN>
__global__ __launch_bounds__(TN == 64 ? 128 : 256, TN == 64 ? 4 : 2)
void mma_gemm(const __nv_bfloat16* __restrict__ A,
              const __nv_bfloat16* __restrict__ B,
              float* __restrict__ C, int ldc, int N, int Kreal,
              int cps, long long partStride)
{
    constexpr int NT   = (TN == 64) ? 128 : 256;
    constexpr int ASZ  = TCM * 64;
    constexpr int BSZ  = TN * 64;
    constexpr int STG  = ASZ + BSZ;
    constexpr int AI   = (TCM * 4) / NT;
    constexpr int BI   = (TN * 4) / NT;

    extern __shared__ __align__(16) char sm[];
    const uint32_t sbase = s2u(sm);
    const int tid  = threadIdx.x;
    const int wid  = tid >> 5, lane = tid & 31;
    const int wm   = wid & 1;
    const int wn   = wid >> 1;
    const int bm   = blockIdx.x * TCM;
    const int bn   = blockIdx.y * TN;
    const int KC   = Kreal / TCK;
    const int c0   = blockIdx.z * cps;
    const int c1   = c0 + cps;
    C += (long long)blockIdx.z * partStride;

    const int lda = 2 * Kreal;

    const __nv_bfloat16* Ag[AI]; uint32_t sa[AI];
    #pragma unroll
    for (int i = 0; i < AI; i++) {
        int v = tid + i * NT, r = v >> 2, k8 = v & 3;
        Ag[i] = A + (size_t)(bm + r) * lda + k8 * 8;
        sa[i] = sbase + swz(r, k8);
    }
    const __nv_bfloat16* Bg[BI]; uint32_t sb[BI];
    #pragma unroll
    for (int i = 0; i < BI; i++) {
        int v = tid + i * NT, r = v >> 2, k8 = v & 3;
        Bg[i] = B + (size_t)(bn + r) * lda + k8 * 8;
        sb[i] = sbase + ASZ + swz(r, k8);
    }

    float acc[4][4][4];
    #pragma unroll
    for (int i = 0; i < 4; i++)
        #pragma unroll
        for (int j = 0; j < 4; j++)
            #pragma unroll
            for (int t = 0; t < 4; t++) acc[i][j][t] = 0.f;

    const int a_row = wm * 64 + (lane & 15);
    const int a_k8s = lane >> 4;
    const int b_row = wn * 32 + (lane & 7) + ((lane >> 4) << 3);
    const int b_k8s = (lane >> 3) & 1;

    #define LOAD_STAGE(cc) do { \
        uint32_t so = (uint32_t)(((cc) - c0) & 3) * STG; \
        int ac = ((cc) < 2*KC ? (cc) : (cc) - 2*KC) * TCK; \
        int bc = ((cc) < KC   ? (cc) : (cc) - KC)   * TCK; \
        _Pragma("unroll") \
        for (int i = 0; i < AI; i++) cp_async16(sa[i] + so, Ag[i] + ac); \
        _Pragma("unroll") \
        for (int i = 0; i < BI; i++) cp_async16(sb[i] + so, Bg[i] + bc); \
        cp_commit(); \
    } while (0)

    #define MATH_STAGE(cc) do { \
        const uint32_t sA = sbase + (uint32_t)(((cc) - c0) & 3) * STG; \
        const uint32_t sB = sA + ASZ; \
        _Pragma("unroll") \
        for (int k16 = 0; k16 < 2; k16++) { \
            uint32_t afrag[4][4]; \
            _Pragma("unroll") \
            for (int mt = 0; mt < 4; mt++) { \
                int row = a_row + mt * 16; \
                ldsm_x4(afrag[mt], sA + swz(row, k16 * 2 + a_k8s)); \
            } \
            uint32_t bfrag[4][2]; \
            _Pragma("unroll") \
            for (int np = 0; np < 2; np++) { \
                int row = b_row + np * 16; \
                uint32_t t[4]; \
                ldsm_x4(t, sB + swz(row, k16 * 2 + b_k8s)); \
                bfrag[np * 2 + 0][0] = t[0]; bfrag[np * 2 + 0][1] = t[1]; \
                bfrag[np * 2 + 1][0] = t[2]; bfrag[np * 2 + 1][1] = t[3]; \
            } \
            _Pragma("unroll") \
            for (int mt = 0; mt < 4; mt++) \
                _Pragma("unroll") \
                for (int nt = 0; nt < 4; nt++) \
                    mma16816(acc[mt][nt], afrag[mt], bfrag[nt]); \
        } \
    } while (0)

    LOAD_STAGE(c0);
    if (c1 - c0 > 1) LOAD_STAGE(c0 + 1);

    for (int c = c0; c < c1; c += 2) {
        cp_wait<0>();
        __syncthreads();
        if (c + 2 < c1) { LOAD_STAGE(c + 2); LOAD_STAGE(c + 3); }
        MATH_STAGE(c);
        MATH_STAGE(c + 1);
    }
    #undef LOAD_STAGE
    #undef MATH_STAGE

    const int erow = lane >> 2;
    const int ecol = (lane & 3) * 2;
    #pragma unroll
    for (int mt = 0; mt < 4; mt++) {
        #pragma unroll
        for (int nt = 0; nt < 4; nt++) {
            int m0 = bm + wm * 64 + mt * 16 + erow;
            int n0 = bn + wn * 32 + nt * 8 + ecol;
            if (n0 < N) {
                float* p0 = C + (size_t)m0 * ldc + n0;
                float* p1 = p0 + 8 * ldc;
                *(float2*)p0 = make_float2(acc[mt][nt][0], acc[mt][nt][1]);
                *(float2*)p1 = make_float2(acc[mt][nt][2], acc[mt][nt][3]);
            }
        }
    }
}

// ---------------- fp16 plain HMMA GEMM (logits), TN=128, K'=K --------------
__global__ __launch_bounds__(256, 2)
void mma_gemm16(const __half* __restrict__ A,
                const __half* __restrict__ B,
                float* __restrict__ C, int ldc, int N, int Kreal)
{
    constexpr int TN   = 128;
    constexpr int NT   = 256;
    constexpr int ASZ  = TCM * 64;
    constexpr int STG  = ASZ + TN * 64;
    constexpr int AI   = (TCM * 4) / NT;   // 2
    constexpr int BI   = (TN * 4) / NT;    // 2

    extern __shared__ __align__(16) char sm[];
    const uint32_t sbase = s2u(sm);
    const int tid  = threadIdx.x;
    const int wid  = tid >> 5, lane = tid & 31;
    const int wm   = wid & 1;
    const int wn   = wid >> 1;
    const int bm   = blockIdx.x * TCM;
    const int bn   = blockIdx.y * TN;
    const int chunks = Kreal / TCK;        // 24
    const int lda  = Kreal;

    const __half* Ag[AI]; uint32_t sa[AI];
    #pragma unroll
    for (int i = 0; i < AI; i++) {
        int v = tid + i * NT, r = v >> 2, k8 = v & 3;
        Ag[i] = A + (size_t)(bm + r) * lda + k8 * 8;
        sa[i] = sbase + swz(r, k8);
    }
    const __half* Bg[BI]; uint32_t sb[BI];
    #pragma unroll
    for (int i = 0; i < BI; i++) {
        int v = tid + i * NT, r = v >> 2, k8 = v & 3;
        Bg[i] = B + (size_t)(bn + r) * lda + k8 * 8;
        sb[i] = sbase + ASZ + swz(r, k8);
    }

    float acc[4][4][4];
    #pragma unroll
    for (int i = 0; i < 4; i++)
        #pragma unroll
        for (int j = 0; j < 4; j++)
            #pragma unroll
            for (int t = 0; t < 4; t++) acc[i][j][t] = 0.f;

    const int a_row = wm * 64 + (lane & 15);
    const int a_k8s = lane >> 4;
    const int b_row = wn * 32 + (lane & 7) + ((lane >> 4) << 3);
    const int b_k8s = (lane >> 3) & 1;

    #define LOAD_STAGE16(cc) do { \
        uint32_t so = (uint32_t)((cc) & 3) * STG; \
        int ko = (cc) * TCK; \
        _Pragma("unroll") \
        for (int i = 0; i < AI; i++) cp_async16(sa[i] + so, Ag[i] + ko); \
        _Pragma("unroll") \
        for (int i = 0; i < BI; i++) cp_async16(sb[i] + so, Bg[i] + ko); \
        cp_commit(); \
    } while (0)

    #define MATH_STAGE16(cc) do { \
        const uint32_t sA = sbase + (uint32_t)((cc) & 3) * STG; \
        const uint32_t sB = sA + ASZ; \
        _Pragma("unroll") \
        for (int k16 = 0; k16 < 2; k16++) { \
            uint32_t afrag[4][4]; \
            _Pragma("unroll") \
            for (int mt = 0; mt < 4; mt++) { \
                int row = a_row + mt * 16; \
                ldsm_x4(afrag[mt], sA + swz(row, k16 * 2 + a_k8s)); \
            } \
            uint32_t bfrag[4][2]; \
            _Pragma("unroll") \
            for (int np = 0; np < 2; np++) { \
                int row = b_row + np * 16; \
                uint32_t t[4]; \
                ldsm_x4(t, sB + swz(row, k16 * 2 + b_k8s)); \
                bfrag[np * 2 + 0][0] = t[0]; bfrag[np * 2 + 0][1] = t[1]; \
                bfrag[np * 2 + 1][0] = t[2]; bfrag[np * 2 + 1][1] = t[3]; \
            } \
            _Pragma("unroll") \
            for (int mt = 0; mt < 4; mt++) \
                _Pragma("unroll") \
                for (int nt = 0; nt < 4; nt++) \
                    mma16816h(acc[mt][nt], afrag[mt], bfrag[nt]); \
        } \
    } while (0)

    LOAD_STAGE16(0);
    LOAD_STAGE16(1);

    for (int c = 0; c < chunks; c += 2) {
        cp_wait<0>();
        __syncthreads();
        if (c + 2 < chunks) { LOAD_STAGE16(c + 2); LOAD_STAGE16(c + 3); }
        MATH_STAGE16(c);
        MATH_STAGE16(c + 1);
    }
    #undef LOAD_STAGE16
    #undef MATH_STAGE16

    const int erow = lane >> 2;
    const int ecol = (lane & 3) * 2;
    #pragma unroll
    for (int mt = 0; mt < 4; mt++) {
        #pragma unroll
        for (int nt = 0; nt < 4; nt++) {
            int m0 = bm + wm * 64 + mt * 16 + erow;
            int n0 = bn + wn * 32 + nt * 8 + ecol;
            if (n0 < N) {
                float* p0 = C + (size_t)m0 * ldc + n0;
                float* p1 = p0 + 8 * ldc;
                *(float2*)p0 = make_float2(acc[mt][nt][0], acc[mt][nt][1]);
                *(float2*)p1 = make_float2(acc[mt][nt][2], acc[mt][nt][3]);
            }
        }
    }
}

#define SMEM64  (4 * (TCM*64 + 64*64))    // 49152
#define SMEM128 (4 * (TCM*64 + 128*64))   // 65536

// ---------------- orchestration --------------------------------------------
extern "C" void kernel_launch(void* const* d_in, const int* in_sizes, int n_in,
                              void* d_out, int out_size)
{
    const int*   ids        = (const int*)  d_in[0];
    const float* emb        = (const float*)d_in[1];
    const float* in_proj_w  = (const float*)d_in[2];
    const float* conv_w     = (const float*)d_in[3];
    const float* conv_b     = (const float*)d_in[4];
    const float* x_proj_w   = (const float*)d_in[5];
    const float* dt_proj_w  = (const float*)d_in[6];
    const float* dt_proj_b  = (const float*)d_in[7];
    const float* A_log      = (const float*)d_in[8];
    const float* D_param    = (const float*)d_in[9];
    const float* out_proj_w = (const float*)d_in[10];
    const float* norm_w     = (const float*)d_in[11];
    const float* norm_f_w   = (const float*)d_in[12];
    float* logits = (float*)d_out;

    cudaFuncSetAttribute(mma_gemm<64>,
                         cudaFuncAttributeMaxDynamicSharedMemorySize, SMEM64);
    cudaFuncSetAttribute(mma_gemm16,
                         cudaFuncAttributeMaxDynamicSharedMemorySize, SMEM128);

    float *h, *xz, *xc, *dbl, *dblp, *dt, *y, *part;
    cudaGetSymbolAddress((void**)&h,    g_h);
    cudaGetSymbolAddress((void**)&xz,   g_xz);
    cudaGetSymbolAddress((void**)&xc,   g_xc);
    cudaGetSymbolAddress((void**)&dbl,  g_dbl);
    cudaGetSymbolAddress((void**)&dblp, g_dblp);
    cudaGetSymbolAddress((void**)&dt,   g_dt);
    cudaGetSymbolAddress((void**)&y,    g_y);
    cudaGetSymbolAddress((void**)&part, g_part);

    __nv_bfloat16 *hn_s, *inw_s, *y_s, *outw_s, *xw_s;
    cudaGetSymbolAddress((void**)&hn_s,   g_hn_s);
    cudaGetSymbolAddress((void**)&inw_s,  g_inw_s);
    cudaGetSymbolAddress((void**)&y_s,    g_y_s);
    cudaGetSymbolAddress((void**)&outw_s, g_outw_s);
    cudaGetSymbolAddress((void**)&xw_s,   g_xw_s);
    __half *emb_h, *hn_h;
    cudaGetSymbolAddress((void**)&emb_h, g_emb_h);
    cudaGetSymbolAddress((void**)&hn_h,  g_hn_h);

    embed_kernel<<<L_SEQ, DM / 4>>>(ids, emb);

    // ---- batched weight/embedding conversions (hoisted) -------------------
    {
        long long t1 = (long long)NLAYER * 2 * DI * DM / 4;
        split2_kernel<<<(unsigned)((t1 + 255) / 256), 256>>>(
            in_proj_w, inw_s, NLAYER * 2 * DI, DM, t1);

        long long t2 = (long long)NLAYER * DM * DI / 4;
        split2_kernel<<<(unsigned)((t2 + 255) / 256), 256>>>(
            out_proj_w, outw_s, NLAYER * DM, DI, t2);

        long long t3 = (long long)NLAYER * 128 * DI / 4;
        split2_xw_kernel<<<(unsigned)((t3 + 255) / 256), 256>>>(x_proj_w);

        long long t4 = (long long)VOCAB_PAD * DM / 4;
        tofp16_kernel<<<(unsigned)((t4 + 255) / 256), 256>>>(
            emb, emb_h, VOCAB, DM, t4);
    }

    for (int i = 0; i < NLAYER; i++) {
        rmsnorm_split_kernel<<<L_SEQ, 256>>>(h, hn_s, norm_w + (size_t)i * DM);

        // xz = hn @ in_proj_w^T   (1024 x 3072, K=768)
        {
            dim3 g1(L_SEQ / TCM, 2 * DI / 64, 1);
            mma_gemm<64><<<g1, 128, SMEM64>>>(
                hn_s, inw_s + (size_t)i * 2 * DI * 2 * DM,
                xz, 2 * DI, 2 * DI, DM, 3 * (DM / TCK), 0);
        }

        conv_silu_kernel<<<(L_SEQ * DI) / 256, 256>>>(
            conv_w + (size_t)i * DI * DCONV, conv_b + (size_t)i * DI);

        // dbl = xc @ x_proj_w^T   (split-K=9, cps=16)
        {
            dim3 g2(L_SEQ / TCM, 2, XPJ_SPLITK);
            mma_gemm<64><<<g2, 128, SMEM64>>>(
                y_s, xw_s + (size_t)i * 128 * 2 * DI,
                dblp, DBL_W, DBL_W, DI,
                3 * (DI / TCK) / XPJ_SPLITK, (long long)L_SEQ * DBL_W);
        }
        combine_dbl_kernel<<<(L_SEQ * DBL_W) / 256, 256>>>();

        // dt = softplus(dbl[:, :48] @ dt_proj_w^T + b)
        {
            dim3 g3((DI + GBN - 1) / GBN, L_SEQ / GBM);
            gemm_tn<1><<<g3, 256>>>(dbl, DBL_W,
                                    dt_proj_w + (size_t)i * DI * DTRANK, DTRANK,
                                    dt, DI, DI, DTRANK,
                                    dt_proj_b + (size_t)i * DI);
        }

        // chunked selective scan
        {
            const float* Al = A_log + (size_t)i * DI * DSTATE;
            dim3 gs(DI / 8, NCHUNK);
            scan_pass1_kernel<<<gs, 128>>>(Al);
            scan_fix_kernel<<<(DI * DSTATE) / 256, 256>>>();
            scan_pass2_kernel<<<gs, 128>>>(Al);
        }

        y_epi_split_kernel<<<(L_SEQ * DI) / 256, 256>>>(D_param + (size_t)i * DI);

        // part[z] = y @ out_proj_w^T, split-K=6 (cps=24)
        {
            dim3 g4(L_SEQ / TCM, DM / 64, 6);
            mma_gemm<64><<<g4, 128, SMEM64>>>(
                y_s, outw_s + (size_t)i * DM * 2 * DI,
                part, DM, DM, DI,
                3 * (DI / TCK) / 6, (long long)L_SEQ * DM);
        }
        combine_h_kernel<<<(L_SEQ * DM) / 256, 256>>>();
    }

    // final rmsnorm -> fp16 hn
    rmsnorm_f16_kernel<<<L_SEQ, 256>>>(h, norm_f_w);

    // logits = hn @ emb^T — plain fp16 GEMM, K=768 (no 3x inflation)
    {
        dim3 g5(L_SEQ / TCM, VOCAB_PAD / 128);
        mma_gemm16<<<g5, 256, SMEM128>>>(hn_h, emb_h, logits, VOCAB, VOCAB, DM);
    }
}

// round 16
// speedup vs baseline: 1.6789x; 1.1603x over previous
#include <cuda_runtime.h>
#include <cuda_bf16.h>
#include <cuda_fp16.h>
#include <math.h>
#include <stdint.h>

#define L_SEQ 1024
#define DM 768
#define DI 1536
#define DSTATE 16
#define DCONV 4
#define DTRANK 48
#define NLAYER 4
#define VOCAB 50280
#define VOCAB_PAD 50304            // 393*128
#define DBL_W (DTRANK + 2*DSTATE)  // 80
#define NCHUNK 32
#define LCHUNK (L_SEQ / NCHUNK)    // 32
#define XPJ_SPLITK 12
#define OPJ_SPLITK 6

// ---------------- scratch (device globals) ---------------------------------
__device__ float g_h [L_SEQ*DM];
__device__ float g_xz[L_SEQ*2*DI];
__device__ float g_xc[L_SEQ*DI];
__device__ float g_dbl[L_SEQ*DBL_W];
__device__ float g_dblp[XPJ_SPLITK * L_SEQ * DBL_W];
__device__ float g_dt[L_SEQ*DI];
__device__ float g_y [L_SEQ*DI];
__device__ float g_part[OPJ_SPLITK * L_SEQ * DM];

// chunked-scan state buffers
__device__ float g_sc_end [NCHUNK*DI*DSTATE];
__device__ float g_sc_prod[NCHUNK*DI*DSTATE];
__device__ float g_sc_start[NCHUNK*DI*DSTATE];

// fp16 exact-A activation buffers: row = [hi | lo], width 2K.
__device__ __half g_hn_s[(size_t)L_SEQ * 2 * DM];
__device__ __half g_y_s [(size_t)L_SEQ * 2 * DI];
// fp16 single-segment weight buffers
__device__ __half g_inw_h [(size_t)NLAYER * 2*DI * DM];
__device__ __half g_outw_h[(size_t)NLAYER * DM   * DI];
__device__ __half g_xw_h  [(size_t)NLAYER * 128  * DI];
// fp16 logits operands
__device__ __half g_emb_h[(size_t)VOCAB_PAD * DM];
__device__ __half g_hn_h [(size_t)L_SEQ * DM];

__device__ __forceinline__ uint32_t s2u(const void* p){
    uint32_t a;
    asm("{ .reg .u64 t; cvta.to.shared.u64 t, %1; cvt.u32.u64 %0, t; }"
        : "=r"(a) : "l"(p));
    return a;
}

// ---------------- embedding gather ----------------------------------------
__global__ void embed_kernel(const int* __restrict__ ids,
                             const float* __restrict__ emb)
{
    int l = blockIdx.x;
    int id = ids[l];
    const float4* src = (const float4*)(emb + (size_t)id * DM);
    float4* dst = (float4*)(g_h + (size_t)l * DM);
    dst[threadIdx.x] = src[threadIdx.x];
}

// ---------------- rmsnorm + fused fp16 [h|l] split (layer path) ------------
__global__ void rmsnorm_split_kernel(const float* __restrict__ in,
                                     __half* __restrict__ out_s,
                                     const float* __restrict__ w)
{
    int l = blockIdx.x;
    const float* x = in + (size_t)l * DM;
    float ss = 0.f;
    for (int i = threadIdx.x; i < DM; i += 256) {
        float v = x[i];
        ss = fmaf(v, v, ss);
    }
    #pragma unroll
    for (int off = 16; off >= 1; off >>= 1)
        ss += __shfl_xor_sync(0xffffffffu, ss, off);

    __shared__ float red[8];
    __shared__ float scale_s;
    int warp = threadIdx.x >> 5, lane = threadIdx.x & 31;
    if (lane == 0) red[warp] = ss;
    __syncthreads();
    if (threadIdx.x == 0) {
        float t = 0.f;
        #pragma unroll
        for (int i = 0; i < 8; i++) t += red[i];
        scale_s = rsqrtf(t / (float)DM + 1e-5f);
    }
    __syncthreads();
    float scale = scale_s;
    __half* row = out_s + (size_t)l * 2 * DM;
    for (int i = threadIdx.x; i < DM; i += 256) {
        float v = x[i] * scale * w[i];
        __half h = __float2half(v);
        __half lo = __float2half(v - __half2float(h));
        row[i]      = h;
        row[DM + i] = lo;
    }
}

// ---------------- final rmsnorm -> fp16 (logits path) ----------------------
__global__ void rmsnorm_f16_kernel(const float* __restrict__ in,
                                   const float* __restrict__ w)
{
    int l = blockIdx.x;
    const float* x = in + (size_t)l * DM;
    float ss = 0.f;
    for (int i = threadIdx.x; i < DM; i += 256) {
        float v = x[i];
        ss = fmaf(v, v, ss);
    }
    #pragma unroll
    for (int off = 16; off >= 1; off >>= 1)
        ss += __shfl_xor_sync(0xffffffffu, ss, off);

    __shared__ float red[8];
    __shared__ float scale_s;
    int warp = threadIdx.x >> 5, lane = threadIdx.x & 31;
    if (lane == 0) red[warp] = ss;
    __syncthreads();
    if (threadIdx.x == 0) {
        float t = 0.f;
        #pragma unroll
        for (int i = 0; i < 8; i++) t += red[i];
        scale_s = rsqrtf(t / (float)DM + 1e-5f);
    }
    __syncthreads();
    float scale = scale_s;
    __half* row = g_hn_h + (size_t)l * DM;
    for (int i = threadIdx.x; i < DM; i += 256)
        row[i] = __float2half(x[i] * scale * w[i]);
}

// ---------------- fp32 -> fp16 dense conversion (zero-pad rows >= R) -------
__global__ void tofp16_kernel(const float* __restrict__ src,
                              __half* __restrict__ dst,
                              int R, int K, long long total4)
{
    long long idx = (long long)blockIdx.x * blockDim.x + threadIdx.x;
    if (idx >= total4) return;
    int kq = K >> 2;
    int r  = (int)(idx / kq);
    float4 v = (r < R) ? ((const float4*)src)[idx]
                       : make_float4(0.f, 0.f, 0.f, 0.f);
    __half2 a = __floats2half2_rn(v.x, v.y);
    __half2 b = __floats2half2_rn(v.z, v.w);
    *(uint2*)(dst + idx * 4) = make_uint2(*(uint32_t*)&a, *(uint32_t*)&b);
}

// x_proj weights -> fp16, per layer pad 80 -> 128 rows
__global__ void tofp16_xw_kernel(const float* __restrict__ xw)
{
    long long idx = (long long)blockIdx.x * blockDim.x + threadIdx.x;  // < 4*128*DI/4
    int kq = DI >> 2;
    int rg = (int)(idx / kq);
    int k4 = (int)(idx - (long long)rg * kq);
    int layer = rg >> 7;
    int r     = rg & 127;
    float4 v = (r < DBL_W)
             ? ((const float4*)(xw + (size_t)layer * DBL_W * DI + (size_t)r * DI))[k4]
             : make_float4(0.f, 0.f, 0.f, 0.f);
    __half2 a = __floats2half2_rn(v.x, v.y);
    __half2 b = __floats2half2_rn(v.z, v.w);
    *(uint2*)(g_xw_h + (size_t)rg * DI + 4 * k4) =
        make_uint2(*(uint32_t*)&a, *(uint32_t*)&b);
}

// ---------------- depthwise causal conv + bias + silu + fused xc split -----
__global__ void conv_silu_kernel(const float* __restrict__ cw,
                                 const float* __restrict__ cb)
{
    int idx = blockIdx.x * blockDim.x + threadIdx.x;
    int l = idx / DI;
    int d = idx - l * DI;
    float4 wv = *(const float4*)(cw + (size_t)d * 4);
    float acc = cb[d];
    const float* wj = (const float*)&wv;
    #pragma unroll
    for (int j = 0; j < DCONV; j++) {
        int ll = l - (DCONV - 1) + j;
        if (ll >= 0) acc = fmaf(wj[j], g_xz[(size_t)ll * 2 * DI + d], acc);
    }
    acc = acc / (1.f + __expf(-acc));
    g_xc[idx] = acc;
    __half h = __float2half(acc);
    __half lo = __float2half(acc - __half2float(h));
    __half* row = g_y_s + (size_t)l * 2 * DI;
    row[d]      = h;
    row[DI + d] = lo;
}

// ---------------- chunked selective scan -----------------------------------
__global__ void scan_pass1_kernel(const float* __restrict__ A_log)
{
    int gw   = threadIdx.x >> 5;
    int lane = threadIdx.x & 31;
    int n    = lane & 15;
    int ch   = (blockIdx.x * 4 + gw) * 2 + (lane >> 4);
    int c    = blockIdx.y;

    float Aval = -__expf(A_log[(size_t)ch * DSTATE + n]);
    float s = 0.f, prod = 1.f;
    int l0 = c * LCHUNK;
    for (int l = l0; l < l0 + LCHUNK; l++) {
        float dtv = g_dt [(size_t)l * DI + ch];
        float xcv = g_xc [(size_t)l * DI + ch];
        float Bv  = g_dbl[(size_t)l * DBL_W + DTRANK + n];
        float dA  = __expf(dtv * Aval);
        s = dA * s + dtv * Bv * xcv;
        prod *= dA;
    }
    int idx = (c * DI + ch) * DSTATE + n;
    g_sc_end[idx]  = s;
    g_sc_prod[idx] = prod;
}

__global__ void scan_fix_kernel()
{
    int i = blockIdx.x * blockDim.x + threadIdx.x;
    float s = 0.f;
    #pragma unroll
    for (int c = 0; c < NCHUNK; c++) {
        g_sc_start[c * DI * DSTATE + i] = s;
        s = g_sc_prod[c * DI * DSTATE + i] * s + g_sc_end[c * DI * DSTATE + i];
    }
}

__global__ void scan_pass2_kernel(const float* __restrict__ A_log)
{
    int gw   = threadIdx.x >> 5;
    int lane = threadIdx.x & 31;
    int n    = lane & 15;
    int ch   = (blockIdx.x * 4 + gw) * 2 + (lane >> 4);
    int c    = blockIdx.y;

    float Aval = -__expf(A_log[(size_t)ch * DSTATE + n]);
    float s = g_sc_start[(c * DI + ch) * DSTATE + n];
    int l0 = c * LCHUNK;
    for (int l = l0; l < l0 + LCHUNK; l++) {
        float dtv = g_dt [(size_t)l * DI + ch];
        float xcv = g_xc [(size_t)l * DI + ch];
        float Bv  = g_dbl[(size_t)l * DBL_W + DTRANK + n];
        float Cv  = g_dbl[(size_t)l * DBL_W + DTRANK + DSTATE + n];
        s = __expf(dtv * Aval) * s + dtv * Bv * xcv;
        float p = s * Cv;
        p += __shfl_xor_sync(0xffffffffu, p, 1);
        p += __shfl_xor_sync(0xffffffffu, p, 2);
        p += __shfl_xor_sync(0xffffffffu, p, 4);
        p += __shfl_xor_sync(0xffffffffu, p, 8);
        if (n == 0) g_y[(size_t)l * DI + ch] = p;
    }
}

// ---------------- y = (y + xc*D) * silu(z), fused fp16 split ---------------
__global__ void y_epi_split_kernel(const float* __restrict__ Dp)
{
    int idx = blockIdx.x * blockDim.x + threadIdx.x;
    int l = idx / DI;
    int d = idx - l * DI;
    float z  = g_xz[(size_t)l * 2 * DI + DI + d];
    float yv = g_y[idx] + g_xc[idx] * Dp[d];
    yv *= z / (1.f + __expf(-z));
    __half h = __float2half(yv);
    __half lo = __float2half(yv - __half2float(h));
    __half* row = g_y_s + (size_t)l * 2 * DI;
    row[d]      = h;
    row[DI + d] = lo;
}

// ---------------- split-K combines -----------------------------------------
__global__ void combine_h_kernel()
{
    int idx = blockIdx.x * blockDim.x + threadIdx.x;
    const int S = L_SEQ * DM;
    float a = 0.f;
    #pragma unroll
    for (int z = 0; z < OPJ_SPLITK; z++) a += g_part[z * S + idx];
    g_h[idx] += a;
}

__global__ void combine_dbl_kernel()
{
    int idx = blockIdx.x * blockDim.x + threadIdx.x;
    const int S = L_SEQ * DBL_W;
    float a = 0.f;
    #pragma unroll
    for (int z = 0; z < XPJ_SPLITK; z++) a += g_dblp[z * S + idx];
    g_dbl[idx] = a;
}

// ---------------- fp32 TN GEMM (dt_proj only) ------------------------------
#define GBM 128
#define GBN 64
#define GBK 16

template<int EPI>
__global__ __launch_bounds__(256)
void gemm_tn(const float* __restrict__ A, int lda,
             const float* __restrict__ B, int ldb,
             float* __restrict__ C, int ldc,
             int N, int K, const float* __restrict__ bias)
{
    __shared__ float As[GBK][GBM + 4];
    __shared__ float Bs[GBK][GBN + 4];

    const int bm  = blockIdx.y * GBM;
    const int bn  = blockIdx.x * GBN;
    const int tid = threadIdx.x;
    const int tx  = tid & 15;
    const int ty  = tid >> 4;
    const int a_row = tid >> 1;
    const int a_k   = (tid & 1) * 8;
    const int b_row = tid >> 2;
    const int b_k   = (tid & 3) * 4;

    float acc[8][4];
    #pragma unroll
    for (int i = 0; i < 8; i++)
        #pragma unroll
        for (int j = 0; j < 4; j++) acc[i][j] = 0.f;

    const float* Aptr = A + (size_t)(bm + a_row) * lda + a_k;
    const int gbn = bn + b_row;
    const float* Bptr = (gbn < N) ? (B + (size_t)gbn * ldb + b_k) : 0;

    for (int k0 = 0; k0 < K; k0 += GBK) {
        float4 av0 = *(const float4*)(Aptr + k0);
        float4 av1 = *(const float4*)(Aptr + k0 + 4);
        float4 bv  = Bptr ? *(const float4*)(Bptr + k0)
                          : make_float4(0.f, 0.f, 0.f, 0.f);

        As[a_k + 0][a_row] = av0.x; As[a_k + 1][a_row] = av0.y;
        As[a_k + 2][a_row] = av0.z; As[a_k + 3][a_row] = av0.w;
        As[a_k + 4][a_row] = av1.x; As[a_k + 5][a_row] = av1.y;
        As[a_k + 6][a_row] = av1.z; As[a_k + 7][a_row] = av1.w;
        Bs[b_k + 0][b_row] = bv.x;  Bs[b_k + 1][b_row] = bv.y;
        Bs[b_k + 2][b_row] = bv.z;  Bs[b_k + 3][b_row] = bv.w;
        __syncthreads();

        #pragma unroll
        for (int kk = 0; kk < GBK; kk++) {
            float ar[8], br[4];
            #pragma unroll
            for (int i = 0; i < 8; i++) ar[i] = As[kk][ty * 8 + i];
            #pragma unroll
            for (int j = 0; j < 4; j++) br[j] = Bs[kk][tx * 4 + j];
            #pragma unroll
            for (int i = 0; i < 8; i++)
                #pragma unroll
                for (int j = 0; j < 4; j++)
                    acc[i][j] = fmaf(ar[i], br[j], acc[i][j]);
        }
        __syncthreads();
    }

    #pragma unroll
    for (int i = 0; i < 8; i++) {
        int m = bm + ty * 8 + i;
        #pragma unroll
        for (int j = 0; j < 4; j++) {
            int n = bn + tx * 4 + j;
            if (n < N) {
                float v = acc[i][j];
                if (EPI == 1) {
                    v += bias[n];
                    v = fmaxf(v, 0.f) + log1pf(__expf(-fabsf(v)));
                }
                C[(size_t)m * ldc + n] = v;
            }
        }
    }
}

// ---------------- tensor-core GEMM common helpers --------------------------
#define TCM 128
#define TCK 32

__device__ __forceinline__ void cp_async16(uint32_t s, const void* g)
{
    asm volatile("cp.async.cg.shared.global [%0], [%1], 16;\n"
                 :: "r"(s), "l"(g));
}
__device__ __forceinline__ void cp_commit(){ asm volatile("cp.async.commit_group;\n" ::: "memory"); }
template<int N> __device__ __forceinline__ void cp_wait(){ asm volatile("cp.async.wait_group %0;\n" :: "n"(N) : "memory"); }

__device__ __forceinline__ void ldsm_x4(uint32_t* r, uint32_t addr)
{
    asm volatile("ldmatrix.sync.aligned.m8n8.x4.shared.b16 {%0,%1,%2,%3}, [%4];"
                 : "=r"(r[0]), "=r"(r[1]), "=r"(r[2]), "=r"(r[3]) : "r"(addr));
}
__device__ __forceinline__ void mma16816h(float* c, const uint32_t* a, const uint32_t* b)
{
    asm volatile(
        "mma.sync.aligned.m16n8k16.row.col.f32.f16.f16.f32 "
        "{%0,%1,%2,%3}, {%4,%5,%6,%7}, {%8,%9}, {%0,%1,%2,%3};"
        : "+f"(c[0]), "+f"(c[1]), "+f"(c[2]), "+f"(c[3])
        : "r"(a[0]), "r"(a[1]), "r"(a[2]), "r"(a[3]), "r"(b[0]), "r"(b[1]));
}

__device__ __forceinline__ uint32_t swz(int row, int chunk){
    return (uint32_t)(row * 64 + ((chunk ^ ((row >> 1) & 3)) * 16));
}

// ---------------- fp16 exact-A GEMM (layer GEMMs): A [Ah|Al], B single -----
// Virtual chunks: 0..2KC-1. a_col = c, b_col = c<KC ? c : c-KC.
template<int TN>
__global__ __launch_bounds__(TN == 64 ? 128 : 256, TN == 64 ? 4 : 2)
void mma_gemm(const __half* __restrict__ A,
              const __half* __restrict__ B,
              float* __restrict__ C, int ldc, int N, int Kreal,
              int cps, long long partStride)
{
    constexpr int NT   = (TN == 64) ? 128 : 256;
    constexpr int ASZ  = TCM * 64;
    constexpr int BSZ  = TN * 64;
    constexpr int STG  = ASZ + BSZ;
    constexpr int AI   = (TCM * 4) / NT;
    constexpr int BI   = (TN * 4) / NT;

    extern __shared__ __align__(16) char sm[];
    const uint32_t sbase = s2u(sm);
    const int tid  = threadIdx.x;
    const int wid  = tid >> 5, lane = tid & 31;
    const int wm   = wid & 1;
    const int wn   = wid >> 1;
    const int bm   = blockIdx.x * TCM;
    const int bn   = blockIdx.y * TN;
    const int KC   = Kreal / TCK;
    const int c0   = blockIdx.z * cps;
    const int c1   = c0 + cps;
    C += (long long)blockIdx.z * partStride;

    const int lda = 2 * Kreal;
    const int ldb = Kreal;

    const __half* Ag[AI]; uint32_t sa[AI];
    #pragma unroll
    for (int i = 0; i < AI; i++) {
        int v = tid + i * NT, r = v >> 2, k8 = v & 3;
        Ag[i] = A + (size_t)(bm + r) * lda + k8 * 8;
        sa[i] = sbase + swz(r, k8);
    }
    const __half* Bg[BI]; uint32_t sb[BI];
    #pragma unroll
    for (int i = 0; i < BI; i++) {
        int v = tid + i * NT, r = v >> 2, k8 = v & 3;
        Bg[i] = B + (size_t)(bn + r) * ldb + k8 * 8;
        sb[i] = sbase + ASZ + swz(r, k8);
    }

    float acc[4][4][4];
    #pragma unroll
    for (int i = 0; i < 4; i++)
        #pragma unroll
        for (int j = 0; j < 4; j++)
            #pragma unroll
            for (int t = 0; t < 4; t++) acc[i][j][t] = 0.f;

    const int a_row = wm * 64 + (lane & 15);
    const int a_k8s = lane >> 4;
    const int b_row = wn * 32 + (lane & 7) + ((lane >> 4) << 3);
    const int b_k8s = (lane >> 3) & 1;

    #define LOAD_STAGE(cc) do { \
        uint32_t so = (uint32_t)(((cc) - c0) & 3) * STG; \
        int ac = (cc) * TCK; \
        int bc = ((cc) < KC ? (cc) : (cc) - KC) * TCK; \
        _Pragma("unroll") \
        for (int i = 0; i < AI; i++) cp_async16(sa[i] + so, Ag[i] + ac); \
        _Pragma("unroll") \
        for (int i = 0; i < BI; i++) cp_async16(sb[i] + so, Bg[i] + bc); \
        cp_commit(); \
    } while (0)

    #define MATH_STAGE(cc) do { \
        const uint32_t sA = sbase + (uint32_t)(((cc) - c0) & 3) * STG; \
        const uint32_t sB = sA + ASZ; \
        _Pragma("unroll") \
        for (int k16 = 0; k16 < 2; k16++) { \
            uint32_t afrag[4][4]; \
            _Pragma("unroll") \
            for (int mt = 0; mt < 4; mt++) { \
                int row = a_row + mt * 16; \
                ldsm_x4(afrag[mt], sA + swz(row, k16 * 2 + a_k8s)); \
            } \
            uint32_t bfrag[4][2]; \
            _Pragma("unroll") \
            for (int np = 0; np < 2; np++) { \
                int row = b_row + np * 16; \
                uint32_t t[4]; \
                ldsm_x4(t, sB + swz(row, k16 * 2 + b_k8s)); \
                bfrag[np * 2 + 0][0] = t[0]; bfrag[np * 2 + 0][1] = t[1]; \
                bfrag[np * 2 + 1][0] = t[2]; bfrag[np * 2 + 1][1] = t[3]; \
            } \
            _Pragma("unroll") \
            for (int mt = 0; mt < 4; mt++) \
                _Pragma("unroll") \
                for (int nt = 0; nt < 4; nt++) \
                    mma16816h(acc[mt][nt], afrag[mt], bfrag[nt]); \
        } \
    } while (0)

    LOAD_STAGE(c0);
    if (c1 - c0 > 1) LOAD_STAGE(c0 + 1);

    for (int c = c0; c < c1; c += 2) {
        cp_wait<0>();
        __syncthreads();
        if (c + 2 < c1) { LOAD_STAGE(c + 2); LOAD_STAGE(c + 3); }
        MATH_STAGE(c);
        MATH_STAGE(c + 1);
    }
    #undef LOAD_STAGE
    #undef MATH_STAGE

    const int erow = lane >> 2;
    const int ecol = (lane & 3) * 2;
    #pragma unroll
    for (int mt = 0; mt < 4; mt++) {
        #pragma unroll
        for (int nt = 0; nt < 4; nt++) {
            int m0 = bm + wm * 64 + mt * 16 + erow;
            int n0 = bn + wn * 32 + nt * 8 + ecol;
            if (n0 < N) {
                float* p0 = C + (size_t)m0 * ldc + n0;
                float* p1 = p0 + 8 * ldc;
                *(float2*)p0 = make_float2(acc[mt][nt][0], acc[mt][nt][1]);
                *(float2*)p1 = make_float2(acc[mt][nt][2], acc[mt][nt][3]);
            }
        }
    }
}

// ---------------- fp16 plain GEMM (logits), TN=128, K'=K -------------------
__global__ __launch_bounds__(256, 2)
void mma_gemm16(const __half* __restrict__ A,
                const __half* __restrict__ B,
                float* __restrict__ C, int ldc, int N, int Kreal)
{
    constexpr int TN   = 128;
    constexpr int NT   = 256;
    constexpr int ASZ  = TCM * 64;
    constexpr int STG  = ASZ + TN * 64;
    constexpr int AI   = (TCM * 4) / NT;
    constexpr int BI   = (TN * 4) / NT;

    extern __shared__ __align__(16) char sm[];
    const uint32_t sbase = s2u(sm);
    const int tid  = threadIdx.x;
    const int wid  = tid >> 5, lane = tid & 31;
    const int wm   = wid & 1;
    const int wn   = wid >> 1;
    const int bm   = blockIdx.x * TCM;
    const int bn   = blockIdx.y * TN;
    const int chunks = Kreal / TCK;
    const int lda  = Kreal;

    const __half* Ag[AI]; uint32_t sa[AI];
    #pragma unroll
    for (int i = 0; i < AI; i++) {
        int v = tid + i * NT, r = v >> 2, k8 = v & 3;
        Ag[i] = A + (size_t)(bm + r) * lda + k8 * 8;
        sa[i] = sbase + swz(r, k8);
    }
    const __half* Bg[BI]; uint32_t sb[BI];
    #pragma unroll
    for (int i = 0; i < BI; i++) {
        int v = tid + i * NT, r = v >> 2, k8 = v & 3;
        Bg[i] = B + (size_t)(bn + r) * lda + k8 * 8;
        sb[i] = sbase + ASZ + swz(r, k8);
    }

    float acc[4][4][4];
    #pragma unroll
    for (int i = 0; i < 4; i++)
        #pragma unroll
        for (int j = 0; j < 4; j++)
            #pragma unroll
            for (int t = 0; t < 4; t++) acc[i][j][t] = 0.f;

    const int a_row = wm * 64 + (lane & 15);
    const int a_k8s = lane >> 4;
    const int b_row = wn * 32 + (lane & 7) + ((lane >> 4) << 3);
    const int b_k8s = (lane >> 3) & 1;

    #define LOAD_STAGE16(cc) do { \
        uint32_t so = (uint32_t)((cc) & 3) * STG; \
        int ko = (cc) * TCK; \
        _Pragma("unroll") \
        for (int i = 0; i < AI; i++) cp_async16(sa[i] + so, Ag[i] + ko); \
        _Pragma("unroll") \
        for (int i = 0; i < BI; i++) cp_async16(sb[i] + so, Bg[i] + ko); \
        cp_commit(); \
    } while (0)

    #define MATH_STAGE16(cc) do { \
        const uint32_t sA = sbase + (uint32_t)((cc) & 3) * STG; \
        const uint32_t sB = sA + ASZ; \
        _Pragma("unroll") \
        for (int k16 = 0; k16 < 2; k16++) { \
            uint32_t afrag[4][4]; \
            _Pragma("unroll") \
            for (int mt = 0; mt < 4; mt++) { \
                int row = a_row + mt * 16; \
                ldsm_x4(afrag[mt], sA + swz(row, k16 * 2 + a_k8s)); \
            } \
            uint32_t bfrag[4][2]; \
            _Pragma("unroll") \
            for (int np = 0; np < 2; np++) { \
                int row = b_row + np * 16; \
                uint32_t t[4]; \
                ldsm_x4(t, sB + swz(row, k16 * 2 + b_k8s)); \
                bfrag[np * 2 + 0][0] = t[0]; bfrag[np * 2 + 0][1] = t[1]; \
                bfrag[np * 2 + 1][0] = t[2]; bfrag[np * 2 + 1][1] = t[3]; \
            } \
            _Pragma("unroll") \
            for (int mt = 0; mt < 4; mt++) \
                _Pragma("unroll") \
                for (int nt = 0; nt < 4; nt++) \
                    mma16816h(acc[mt][nt], afrag[mt], bfrag[nt]); \
        } \
    } while (0)

    LOAD_STAGE16(0);
    LOAD_STAGE16(1);

    for (int c = 0; c < chunks; c += 2) {
        cp_wait<0>();
        __syncthreads();
        if (c + 2 < chunks) { LOAD_STAGE16(c + 2); LOAD_STAGE16(c + 3); }
        MATH_STAGE16(c);
        MATH_STAGE16(c + 1);
    }
    #undef LOAD_STAGE16
    #undef MATH_STAGE16

    const int erow = lane >> 2;
    const int ecol = (lane & 3) * 2;
    #pragma unroll
    for (int mt = 0; mt < 4; mt++) {
        #pragma unroll
        for (int nt = 0; nt < 4; nt++) {
            int m0 = bm + wm * 64 + mt * 16 + erow;
            int n0 = bn + wn * 32 + nt * 8 + ecol;
            if (n0 < N) {
                float* p0 = C + (size_t)m0 * ldc + n0;
                float* p1 = p0 + 8 * ldc;
                *(float2*)p0 = make_float2(acc[mt][nt][0], acc[mt][nt][1]);
                *(float2*)p1 = make_float2(acc[mt][nt][2], acc[mt][nt][3]);
            }
        }
    }
}

#define SMEM64  (4 * (TCM*64 + 64*64))    // 49152
#define SMEM128 (4 * (TCM*64 + 128*64))   // 65536

// ---------------- orchestration --------------------------------------------
extern "C" void kernel_launch(void* const* d_in, const int* in_sizes, int n_in,
                              void* d_out, int out_size)
{
    const int*   ids        = (const int*)  d_in[0];
    const float* emb        = (const float*)d_in[1];
    const float* in_proj_w  = (const float*)d_in[2];
    const float* conv_w     = (const float*)d_in[3];
    const float* conv_b     = (const float*)d_in[4];
    const float* x_proj_w   = (const float*)d_in[5];
    const float* dt_proj_w  = (const float*)d_in[6];
    const float* dt_proj_b  = (const float*)d_in[7];
    const float* A_log      = (const float*)d_in[8];
    const float* D_param    = (const float*)d_in[9];
    const float* out_proj_w = (const float*)d_in[10];
    const float* norm_w     = (const float*)d_in[11];
    const float* norm_f_w   = (const float*)d_in[12];
    float* logits = (float*)d_out;

    cudaFuncSetAttribute(mma_gemm<64>,
                         cudaFuncAttributeMaxDynamicSharedMemorySize, SMEM64);
    cudaFuncSetAttribute(mma_gemm16,
                         cudaFuncAttributeMaxDynamicSharedMemorySize, SMEM128);

    float *h, *xz, *xc, *dbl, *dblp, *dt, *y, *part;
    cudaGetSymbolAddress((void**)&h,    g_h);
    cudaGetSymbolAddress((void**)&xz,   g_xz);
    cudaGetSymbolAddress((void**)&xc,   g_xc);
    cudaGetSymbolAddress((void**)&dbl,  g_dbl);
    cudaGetSymbolAddress((void**)&dblp, g_dblp);
    cudaGetSymbolAddress((void**)&dt,   g_dt);
    cudaGetSymbolAddress((void**)&y,    g_y);
    cudaGetSymbolAddress((void**)&part, g_part);

    __half *hn_s, *y_s, *inw_h, *outw_h, *xw_h, *emb_h, *hn_h;
    cudaGetSymbolAddress((void**)&hn_s,   g_hn_s);
    cudaGetSymbolAddress((void**)&y_s,    g_y_s);
    cudaGetSymbolAddress((void**)&inw_h,  g_inw_h);
    cudaGetSymbolAddress((void**)&outw_h, g_outw_h);
    cudaGetSymbolAddress((void**)&xw_h,   g_xw_h);
    cudaGetSymbolAddress((void**)&emb_h,  g_emb_h);
    cudaGetSymbolAddress((void**)&hn_h,   g_hn_h);

    embed_kernel<<<L_SEQ, DM / 4>>>(ids, emb);

    // ---- batched weight/embedding fp16 conversions (hoisted) --------------
    {
        long long t1 = (long long)NLAYER * 2 * DI * DM / 4;
        tofp16_kernel<<<(unsigned)((t1 + 255) / 256), 256>>>(
            in_proj_w, inw_h, NLAYER * 2 * DI, DM, t1);

        long long t2 = (long long)NLAYER * DM * DI / 4;
        tofp16_kernel<<<(unsigned)((t2 + 255) / 256), 256>>>(
            out_proj_w, outw_h, NLAYER * DM, DI, t2);

        long long t3 = (long long)NLAYER * 128 * DI / 4;
        tofp16_xw_kernel<<<(unsigned)((t3 + 255) / 256), 256>>>(x_proj_w);

        long long t4 = (long long)VOCAB_PAD * DM / 4;
        tofp16_kernel<<<(unsigned)((t4 + 255) / 256), 256>>>(
            emb, emb_h, VOCAB, DM, t4);
    }

    for (int i = 0; i < NLAYER; i++) {
        rmsnorm_split_kernel<<<L_SEQ, 256>>>(h, hn_s, norm_w + (size_t)i * DM);

        // xz = hn @ in_proj_w^T   (1024 x 3072, K=768, 48 virtual chunks)
        {
            dim3 g1(L_SEQ / TCM, 2 * DI / 64, 1);
            mma_gemm<64><<<g1, 128, SMEM64>>>(
                hn_s, inw_h + (size_t)i * 2 * DI * DM,
                xz, 2 * DI, 2 * DI, DM, 2 * (DM / TCK), 0);
        }

        conv_silu_kernel<<<(L_SEQ * DI) / 256, 256>>>(
            conv_w + (size_t)i * DI * DCONV, conv_b + (size_t)i * DI);

        // dbl = xc @ x_proj_w^T   (96 chunks, split-K=12, cps=8)
        {
            dim3 g2(L_SEQ / TCM, 2, XPJ_SPLITK);
            mma_gemm<64><<<g2, 128, SMEM64>>>(
                y_s, xw_h + (size_t)i * 128 * DI,
                dblp, DBL_W, DBL_W, DI,
                2 * (DI / TCK) / XPJ_SPLITK, (long long)L_SEQ * DBL_W);
        }
        combine_dbl_kernel<<<(L_SEQ * DBL_W) / 256, 256>>>();

        // dt = softplus(dbl[:, :48] @ dt_proj_w^T + b)
        {
            dim3 g3((DI + GBN - 1) / GBN, L_SEQ / GBM);
            gemm_tn<1><<<g3, 256>>>(dbl, DBL_W,
                                    dt_proj_w + (size_t)i * DI * DTRANK, DTRANK,
                                    dt, DI, DI, DTRANK,
                                    dt_proj_b + (size_t)i * DI);
        }

        // chunked selective scan (32 chunks of 32)
        {
            const float* Al = A_log + (size_t)i * DI * DSTATE;
            dim3 gs(DI / 8, NCHUNK);
            scan_pass1_kernel<<<gs, 128>>>(Al);
            scan_fix_kernel<<<(DI * DSTATE) / 256, 256>>>();
            scan_pass2_kernel<<<gs, 128>>>(Al);
        }

        y_epi_split_kernel<<<(L_SEQ * DI) / 256, 256>>>(D_param + (size_t)i * DI);

        // part[z] = y @ out_proj_w^T  (96 chunks, split-K=6, cps=16)
        {
            dim3 g4(L_SEQ / TCM, DM / 64, OPJ_SPLITK);
            mma_gemm<64><<<g4, 128, SMEM64>>>(
                y_s, outw_h + (size_t)i * DM * DI,
                part, DM, DM, DI,
                2 * (DI / TCK) / OPJ_SPLITK, (long long)L_SEQ * DM);
        }
        combine_h_kernel<<<(L_SEQ * DM) / 256, 256>>>();
    }

    // final rmsnorm -> fp16 hn
    rmsnorm_f16_kernel<<<L_SEQ, 256>>>(h, norm_f_w);

    // logits = hn @ emb^T — plain fp16 GEMM, K=768
    {
        dim3 g5(L_SEQ / TCM, VOCAB_PAD / 128);
        mma_gemm16<<<g5, 256, SMEM128>>>(hn_h, emb_h, logits, VOCAB, VOCAB, DM);
    }
}

// round 17
// speedup vs baseline: 1.8477x; 1.1006x over previous
#include <cuda_runtime.h>
#include <cuda_fp16.h>
#include <math.h>
#include <stdint.h>

#define L_SEQ 1024
#define DM 768
#define DI 1536
#define DSTATE 16
#define DCONV 4
#define DTRANK 48
#define NLAYER 4
#define VOCAB 50280
#define VOCAB_PAD 50304            // 393*128
#define DBL_W (DTRANK + 2*DSTATE)  // 80
#define NCHUNK 32
#define LCHUNK (L_SEQ / NCHUNK)    // 32
#define XPJ_SPLITK 12
#define OPJ_SPLITK 6

// ---------------- scratch (device globals) ---------------------------------
__device__ float g_h [L_SEQ*DM];
__device__ float g_xz[L_SEQ*2*DI];
__device__ float g_xc[L_SEQ*DI];
__device__ float g_dbl[L_SEQ*DBL_W];
__device__ float g_dblp[XPJ_SPLITK * L_SEQ * DBL_W];
__device__ float g_dt[L_SEQ*DI];
__device__ float g_y [L_SEQ*DI];
__device__ float g_part[OPJ_SPLITK * L_SEQ * DM];

// chunked-scan state buffers
__device__ float g_sc_end [NCHUNK*DI*DSTATE];
__device__ float g_sc_prod[NCHUNK*DI*DSTATE];
__device__ float g_sc_start[NCHUNK*DI*DSTATE];

// fp16 operands (single segment everywhere)
__device__ __half g_hn_h [(size_t)L_SEQ * DM];
__device__ __half g_y_h  [(size_t)L_SEQ * DI];
__device__ __half g_inw_h [(size_t)NLAYER * 2*DI * DM];
__device__ __half g_outw_h[(size_t)NLAYER * DM   * DI];
__device__ __half g_xw_h  [(size_t)NLAYER * 128  * DI];
__device__ __half g_emb_h[(size_t)VOCAB_PAD * DM];

__device__ __forceinline__ uint32_t s2u(const void* p){
    uint32_t a;
    asm("{ .reg .u64 t; cvta.to.shared.u64 t, %1; cvt.u32.u64 %0, t; }"
        : "=r"(a) : "l"(p));
    return a;
}

// ---------------- embedding gather ----------------------------------------
__global__ void embed_kernel(const int* __restrict__ ids,
                             const float* __restrict__ emb)
{
    int l = blockIdx.x;
    int id = ids[l];
    const float4* src = (const float4*)(emb + (size_t)id * DM);
    float4* dst = (float4*)(g_h + (size_t)l * DM);
    dst[threadIdx.x] = src[threadIdx.x];
}

// ---------------- rmsnorm -> fp16 ------------------------------------------
__global__ void rmsnorm_f16_kernel(const float* __restrict__ in,
                                   __half* __restrict__ out,
                                   const float* __restrict__ w)
{
    int l = blockIdx.x;
    const float* x = in + (size_t)l * DM;
    float ss = 0.f;
    for (int i = threadIdx.x; i < DM; i += 256) {
        float v = x[i];
        ss = fmaf(v, v, ss);
    }
    #pragma unroll
    for (int off = 16; off >= 1; off >>= 1)
        ss += __shfl_xor_sync(0xffffffffu, ss, off);

    __shared__ float red[8];
    __shared__ float scale_s;
    int warp = threadIdx.x >> 5, lane = threadIdx.x & 31;
    if (lane == 0) red[warp] = ss;
    __syncthreads();
    if (threadIdx.x == 0) {
        float t = 0.f;
        #pragma unroll
        for (int i = 0; i < 8; i++) t += red[i];
        scale_s = rsqrtf(t / (float)DM + 1e-5f);
    }
    __syncthreads();
    float scale = scale_s;
    __half* row = out + (size_t)l * DM;
    for (int i = threadIdx.x; i < DM; i += 256)
        row[i] = __float2half(x[i] * scale * w[i]);
}

// ---------------- fp32 -> fp16 dense conversion (zero-pad rows >= R) -------
__global__ void tofp16_kernel(const float* __restrict__ src,
                              __half* __restrict__ dst,
                              int R, int K, long long total4)
{
    long long idx = (long long)blockIdx.x * blockDim.x + threadIdx.x;
    if (idx >= total4) return;
    int kq = K >> 2;
    int r  = (int)(idx / kq);
    float4 v = (r < R) ? ((const float4*)src)[idx]
                       : make_float4(0.f, 0.f, 0.f, 0.f);
    __half2 a = __floats2half2_rn(v.x, v.y);
    __half2 b = __floats2half2_rn(v.z, v.w);
    *(uint2*)(dst + idx * 4) = make_uint2(*(uint32_t*)&a, *(uint32_t*)&b);
}

// x_proj weights -> fp16, per layer pad 80 -> 128 rows
__global__ void tofp16_xw_kernel(const float* __restrict__ xw)
{
    long long idx = (long long)blockIdx.x * blockDim.x + threadIdx.x;
    int kq = DI >> 2;
    int rg = (int)(idx / kq);
    int k4 = (int)(idx - (long long)rg * kq);
    int layer = rg >> 7;
    int r     = rg & 127;
    float4 v = (r < DBL_W)
             ? ((const float4*)(xw + (size_t)layer * DBL_W * DI + (size_t)r * DI))[k4]
             : make_float4(0.f, 0.f, 0.f, 0.f);
    __half2 a = __floats2half2_rn(v.x, v.y);
    __half2 b = __floats2half2_rn(v.z, v.w);
    *(uint2*)(g_xw_h + (size_t)rg * DI + 4 * k4) =
        make_uint2(*(uint32_t*)&a, *(uint32_t*)&b);
}

// ---------------- depthwise causal conv + bias + silu + fp16 copy ----------
__global__ void conv_silu_kernel(const float* __restrict__ cw,
                                 const float* __restrict__ cb)
{
    int idx = blockIdx.x * blockDim.x + threadIdx.x;
    int l = idx / DI;
    int d = idx - l * DI;
    float4 wv = *(const float4*)(cw + (size_t)d * 4);
    float acc = cb[d];
    const float* wj = (const float*)&wv;
    #pragma unroll
    for (int j = 0; j < DCONV; j++) {
        int ll = l - (DCONV - 1) + j;
        if (ll >= 0) acc = fmaf(wj[j], g_xz[(size_t)ll * 2 * DI + d], acc);
    }
    acc = acc / (1.f + __expf(-acc));
    g_xc[idx] = acc;
    g_y_h[idx] = __float2half(acc);
}

// ---------------- chunked selective scan -----------------------------------
__global__ void scan_pass1_kernel(const float* __restrict__ A_log)
{
    int gw   = threadIdx.x >> 5;
    int lane = threadIdx.x & 31;
    int n    = lane & 15;
    int ch   = (blockIdx.x * 4 + gw) * 2 + (lane >> 4);
    int c    = blockIdx.y;

    float Aval = -__expf(A_log[(size_t)ch * DSTATE + n]);
    float s = 0.f, prod = 1.f;
    int l0 = c * LCHUNK;
    for (int l = l0; l < l0 + LCHUNK; l++) {
        float dtv = g_dt [(size_t)l * DI + ch];
        float xcv = g_xc [(size_t)l * DI + ch];
        float Bv  = g_dbl[(size_t)l * DBL_W + DTRANK + n];
        float dA  = __expf(dtv * Aval);
        s = dA * s + dtv * Bv * xcv;
        prod *= dA;
    }
    int idx = (c * DI + ch) * DSTATE + n;
    g_sc_end[idx]  = s;
    g_sc_prod[idx] = prod;
}

__global__ void scan_fix_kernel()
{
    int i = blockIdx.x * blockDim.x + threadIdx.x;
    float s = 0.f;
    #pragma unroll
    for (int c = 0; c < NCHUNK; c++) {
        g_sc_start[c * DI * DSTATE + i] = s;
        s = g_sc_prod[c * DI * DSTATE + i] * s + g_sc_end[c * DI * DSTATE + i];
    }
}

__global__ void scan_pass2_kernel(const float* __restrict__ A_log)
{
    int gw   = threadIdx.x >> 5;
    int lane = threadIdx.x & 31;
    int n    = lane & 15;
    int ch   = (blockIdx.x * 4 + gw) * 2 + (lane >> 4);
    int c    = blockIdx.y;

    float Aval = -__expf(A_log[(size_t)ch * DSTATE + n]);
    float s = g_sc_start[(c * DI + ch) * DSTATE + n];
    int l0 = c * LCHUNK;
    for (int l = l0; l < l0 + LCHUNK; l++) {
        float dtv = g_dt [(size_t)l * DI + ch];
        float xcv = g_xc [(size_t)l * DI + ch];
        float Bv  = g_dbl[(size_t)l * DBL_W + DTRANK + n];
        float Cv  = g_dbl[(size_t)l * DBL_W + DTRANK + DSTATE + n];
        s = __expf(dtv * Aval) * s + dtv * Bv * xcv;
        float p = s * Cv;
        p += __shfl_xor_sync(0xffffffffu, p, 1);
        p += __shfl_xor_sync(0xffffffffu, p, 2);
        p += __shfl_xor_sync(0xffffffffu, p, 4);
        p += __shfl_xor_sync(0xffffffffu, p, 8);
        if (n == 0) g_y[(size_t)l * DI + ch] = p;
    }
}

// ---------------- y = (y + xc*D) * silu(z) -> fp16 -------------------------
__global__ void y_epi_kernel(const float* __restrict__ Dp)
{
    int idx = blockIdx.x * blockDim.x + threadIdx.x;
    int l = idx / DI;
    int d = idx - l * DI;
    float z  = g_xz[(size_t)l * 2 * DI + DI + d];
    float yv = g_y[idx] + g_xc[idx] * Dp[d];
    yv *= z / (1.f + __expf(-z));
    g_y_h[idx] = __float2half(yv);
}

// ---------------- split-K combines -----------------------------------------
__global__ void combine_h_kernel()
{
    int idx = blockIdx.x * blockDim.x + threadIdx.x;
    const int S = L_SEQ * DM;
    float a = 0.f;
    #pragma unroll
    for (int z = 0; z < OPJ_SPLITK; z++) a += g_part[z * S + idx];
    g_h[idx] += a;
}

__global__ void combine_dbl_kernel()
{
    int idx = blockIdx.x * blockDim.x + threadIdx.x;
    const int S = L_SEQ * DBL_W;
    float a = 0.f;
    #pragma unroll
    for (int z = 0; z < XPJ_SPLITK; z++) a += g_dblp[z * S + idx];
    g_dbl[idx] = a;
}

// ---------------- fp32 TN GEMM (dt_proj only) ------------------------------
#define GBM 128
#define GBN 64
#define GBK 16

template<int EPI>
__global__ __launch_bounds__(256)
void gemm_tn(const float* __restrict__ A, int lda,
             const float* __restrict__ B, int ldb,
             float* __restrict__ C, int ldc,
             int N, int K, const float* __restrict__ bias)
{
    __shared__ float As[GBK][GBM + 4];
    __shared__ float Bs[GBK][GBN + 4];

    const int bm  = blockIdx.y * GBM;
    const int bn  = blockIdx.x * GBN;
    const int tid = threadIdx.x;
    const int tx  = tid & 15;
    const int ty  = tid >> 4;
    const int a_row = tid >> 1;
    const int a_k   = (tid & 1) * 8;
    const int b_row = tid >> 2;
    const int b_k   = (tid & 3) * 4;

    float acc[8][4];
    #pragma unroll
    for (int i = 0; i < 8; i++)
        #pragma unroll
        for (int j = 0; j < 4; j++) acc[i][j] = 0.f;

    const float* Aptr = A + (size_t)(bm + a_row) * lda + a_k;
    const int gbn = bn + b_row;
    const float* Bptr = (gbn < N) ? (B + (size_t)gbn * ldb + b_k) : 0;

    for (int k0 = 0; k0 < K; k0 += GBK) {
        float4 av0 = *(const float4*)(Aptr + k0);
        float4 av1 = *(const float4*)(Aptr + k0 + 4);
        float4 bv  = Bptr ? *(const float4*)(Bptr + k0)
                          : make_float4(0.f, 0.f, 0.f, 0.f);

        As[a_k + 0][a_row] = av0.x; As[a_k + 1][a_row] = av0.y;
        As[a_k + 2][a_row] = av0.z; As[a_k + 3][a_row] = av0.w;
        As[a_k + 4][a_row] = av1.x; As[a_k + 5][a_row] = av1.y;
        As[a_k + 6][a_row] = av1.z; As[a_k + 7][a_row] = av1.w;
        Bs[b_k + 0][b_row] = bv.x;  Bs[b_k + 1][b_row] = bv.y;
        Bs[b_k + 2][b_row] = bv.z;  Bs[b_k + 3][b_row] = bv.w;
        __syncthreads();

        #pragma unroll
        for (int kk = 0; kk < GBK; kk++) {
            float ar[8], br[4];
            #pragma unroll
            for (int i = 0; i < 8; i++) ar[i] = As[kk][ty * 8 + i];
            #pragma unroll
            for (int j = 0; j < 4; j++) br[j] = Bs[kk][tx * 4 + j];
            #pragma unroll
            for (int i = 0; i < 8; i++)
                #pragma unroll
                for (int j = 0; j < 4; j++)
                    acc[i][j] = fmaf(ar[i], br[j], acc[i][j]);
        }
        __syncthreads();
    }

    #pragma unroll
    for (int i = 0; i < 8; i++) {
        int m = bm + ty * 8 + i;
        #pragma unroll
        for (int j = 0; j < 4; j++) {
            int n = bn + tx * 4 + j;
            if (n < N) {
                float v = acc[i][j];
                if (EPI == 1) {
                    v += bias[n];
                    v = fmaxf(v, 0.f) + log1pf(__expf(-fabsf(v)));
                }
                C[(size_t)m * ldc + n] = v;
            }
        }
    }
}

// ---------------- fp16 HMMA GEMM, templated N tile, 4-stage pair loop ------
// Plain fp16 both operands, K' = K. Split-K via blockIdx.z (cps even).
#define TCM 128
#define TCK 32

__device__ __forceinline__ void cp_async16(uint32_t s, const void* g)
{
    asm volatile("cp.async.cg.shared.global [%0], [%1], 16;\n"
                 :: "r"(s), "l"(g));
}
__device__ __forceinline__ void cp_commit(){ asm volatile("cp.async.commit_group;\n" ::: "memory"); }
template<int N> __device__ __forceinline__ void cp_wait(){ asm volatile("cp.async.wait_group %0;\n" :: "n"(N) : "memory"); }

__device__ __forceinline__ void ldsm_x4(uint32_t* r, uint32_t addr)
{
    asm volatile("ldmatrix.sync.aligned.m8n8.x4.shared.b16 {%0,%1,%2,%3}, [%4];"
                 : "=r"(r[0]), "=r"(r[1]), "=r"(r[2]), "=r"(r[3]) : "r"(addr));
}
__device__ __forceinline__ void mma16816h(float* c, const uint32_t* a, const uint32_t* b)
{
    asm volatile(
        "mma.sync.aligned.m16n8k16.row.col.f32.f16.f16.f32 "
        "{%0,%1,%2,%3}, {%4,%5,%6,%7}, {%8,%9}, {%0,%1,%2,%3};"
        : "+f"(c[0]), "+f"(c[1]), "+f"(c[2]), "+f"(c[3])
        : "r"(a[0]), "r"(a[1]), "r"(a[2]), "r"(a[3]), "r"(b[0]), "r"(b[1]));
}

__device__ __forceinline__ uint32_t swz(int row, int chunk){
    return (uint32_t)(row * 64 + ((chunk ^ ((row >> 1) & 3)) * 16));
}

template<int TN>
__global__ __launch_bounds__(TN == 64 ? 128 : 256, TN == 64 ? 4 : 2)
void mma_gemm(const __half* __restrict__ A,
              const __half* __restrict__ B,
              float* __restrict__ C, int ldc, int N, int Kreal,
              int cps, long long partStride)
{
    constexpr int NT   = (TN == 64) ? 128 : 256;
    constexpr int ASZ  = TCM * 64;
    constexpr int BSZ  = TN * 64;
    constexpr int STG  = ASZ + BSZ;
    constexpr int AI   = (TCM * 4) / NT;
    constexpr int BI   = (TN * 4) / NT;

    extern __shared__ __align__(16) char sm[];
    const uint32_t sbase = s2u(sm);
    const int tid  = threadIdx.x;
    const int wid  = tid >> 5, lane = tid & 31;
    const int wm   = wid & 1;
    const int wn   = wid >> 1;
    const int bm   = blockIdx.x * TCM;
    const int bn   = blockIdx.y * TN;
    const int c0   = blockIdx.z * cps;
    const int c1   = c0 + cps;
    C += (long long)blockIdx.z * partStride;

    const int lda = Kreal;

    const __half* Ag[AI]; uint32_t sa[AI];
    #pragma unroll
    for (int i = 0; i < AI; i++) {
        int v = tid + i * NT, r = v >> 2, k8 = v & 3;
        Ag[i] = A + (size_t)(bm + r) * lda + k8 * 8;
        sa[i] = sbase + swz(r, k8);
    }
    const __half* Bg[BI]; uint32_t sb[BI];
    #pragma unroll
    for (int i = 0; i < BI; i++) {
        int v = tid + i * NT, r = v >> 2, k8 = v & 3;
        Bg[i] = B + (size_t)(bn + r) * lda + k8 * 8;
        sb[i] = sbase + ASZ + swz(r, k8);
    }

    float acc[4][4][4];
    #pragma unroll
    for (int i = 0; i < 4; i++)
        #pragma unroll
        for (int j = 0; j < 4; j++)
            #pragma unroll
            for (int t = 0; t < 4; t++) acc[i][j][t] = 0.f;

    const int a_row = wm * 64 + (lane & 15);
    const int a_k8s = lane >> 4;
    const int b_row = wn * 32 + (lane & 7) + ((lane >> 4) << 3);
    const int b_k8s = (lane >> 3) & 1;

    #define LOAD_STAGE(cc) do { \
        uint32_t so = (uint32_t)(((cc) - c0) & 3) * STG; \
        int ko = (cc) * TCK; \
        _Pragma("unroll") \
        for (int i = 0; i < AI; i++) cp_async16(sa[i] + so, Ag[i] + ko); \
        _Pragma("unroll") \
        for (int i = 0; i < BI; i++) cp_async16(sb[i] + so, Bg[i] + ko); \
        cp_commit(); \
    } while (0)

    #define MATH_STAGE(cc) do { \
        const uint32_t sA = sbase + (uint32_t)(((cc) - c0) & 3) * STG; \
        const uint32_t sB = sA + ASZ; \
        _Pragma("unroll") \
        for (int k16 = 0; k16 < 2; k16++) { \
            uint32_t afrag[4][4]; \
            _Pragma("unroll") \
            for (int mt = 0; mt < 4; mt++) { \
                int row = a_row + mt * 16; \
                ldsm_x4(afrag[mt], sA + swz(row, k16 * 2 + a_k8s)); \
            } \
            uint32_t bfrag[4][2]; \
            _Pragma("unroll") \
            for (int np = 0; np < 2; np++) { \
                int row = b_row + np * 16; \
                uint32_t t[4]; \
                ldsm_x4(t, sB + swz(row, k16 * 2 + b_k8s)); \
                bfrag[np * 2 + 0][0] = t[0]; bfrag[np * 2 + 0][1] = t[1]; \
                bfrag[np * 2 + 1][0] = t[2]; bfrag[np * 2 + 1][1] = t[3]; \
            } \
            _Pragma("unroll") \
            for (int mt = 0; mt < 4; mt++) \
                _Pragma("unroll") \
                for (int nt = 0; nt < 4; nt++) \
                    mma16816h(acc[mt][nt], afrag[mt], bfrag[nt]); \
        } \
    } while (0)

    LOAD_STAGE(c0);
    if (c1 - c0 > 1) LOAD_STAGE(c0 + 1);

    for (int c = c0; c < c1; c += 2) {
        cp_wait<0>();
        __syncthreads();
        if (c + 2 < c1) { LOAD_STAGE(c + 2); LOAD_STAGE(c + 3); }
        MATH_STAGE(c);
        MATH_STAGE(c + 1);
    }
    #undef LOAD_STAGE
    #undef MATH_STAGE

    const int erow = lane >> 2;
    const int ecol = (lane & 3) * 2;
    #pragma unroll
    for (int mt = 0; mt < 4; mt++) {
        #pragma unroll
        for (int nt = 0; nt < 4; nt++) {
            int m0 = bm + wm * 64 + mt * 16 + erow;
            int n0 = bn + wn * 32 + nt * 8 + ecol;
            if (n0 < N) {
                float* p0 = C + (size_t)m0 * ldc + n0;
                float* p1 = p0 + 8 * ldc;
                *(float2*)p0 = make_float2(acc[mt][nt][0], acc[mt][nt][1]);
                *(float2*)p1 = make_float2(acc[mt][nt][2], acc[mt][nt][3]);
            }
        }
    }
}

#define SMEM64  (4 * (TCM*64 + 64*64))    // 49152
#define SMEM128 (4 * (TCM*64 + 128*64))   // 65536

// ---------------- orchestration --------------------------------------------
extern "C" void kernel_launch(void* const* d_in, const int* in_sizes, int n_in,
                              void* d_out, int out_size)
{
    const int*   ids        = (const int*)  d_in[0];
    const float* emb        = (const float*)d_in[1];
    const float* in_proj_w  = (const float*)d_in[2];
    const float* conv_w     = (const float*)d_in[3];
    const float* conv_b     = (const float*)d_in[4];
    const float* x_proj_w   = (const float*)d_in[5];
    const float* dt_proj_w  = (const float*)d_in[6];
    const float* dt_proj_b  = (const float*)d_in[7];
    const float* A_log      = (const float*)d_in[8];
    const float* D_param    = (const float*)d_in[9];
    const float* out_proj_w = (const float*)d_in[10];
    const float* norm_w     = (const float*)d_in[11];
    const float* norm_f_w   = (const float*)d_in[12];
    float* logits = (float*)d_out;

    cudaFuncSetAttribute(mma_gemm<64>,
                         cudaFuncAttributeMaxDynamicSharedMemorySize, SMEM64);
    cudaFuncSetAttribute(mma_gemm<128>,
                         cudaFuncAttributeMaxDynamicSharedMemorySize, SMEM128);

    float *h, *xz, *xc, *dbl, *dblp, *dt, *y, *part;
    cudaGetSymbolAddress((void**)&h,    g_h);
    cudaGetSymbolAddress((void**)&xz,   g_xz);
    cudaGetSymbolAddress((void**)&xc,   g_xc);
    cudaGetSymbolAddress((void**)&dbl,  g_dbl);
    cudaGetSymbolAddress((void**)&dblp, g_dblp);
    cudaGetSymbolAddress((void**)&dt,   g_dt);
    cudaGetSymbolAddress((void**)&y,    g_y);
    cudaGetSymbolAddress((void**)&part, g_part);

    __half *hn_h, *y_h, *inw_h, *outw_h, *xw_h, *emb_h;
    cudaGetSymbolAddress((void**)&hn_h,   g_hn_h);
    cudaGetSymbolAddress((void**)&y_h,    g_y_h);
    cudaGetSymbolAddress((void**)&inw_h,  g_inw_h);
    cudaGetSymbolAddress((void**)&outw_h, g_outw_h);
    cudaGetSymbolAddress((void**)&xw_h,   g_xw_h);
    cudaGetSymbolAddress((void**)&emb_h,  g_emb_h);

    embed_kernel<<<L_SEQ, DM / 4>>>(ids, emb);

    // ---- batched weight/embedding fp16 conversions (hoisted) --------------
    {
        long long t1 = (long long)NLAYER * 2 * DI * DM / 4;
        tofp16_kernel<<<(unsigned)((t1 + 255) / 256), 256>>>(
            in_proj_w, inw_h, NLAYER * 2 * DI, DM, t1);

        long long t2 = (long long)NLAYER * DM * DI / 4;
        tofp16_kernel<<<(unsigned)((t2 + 255) / 256), 256>>>(
            out_proj_w, outw_h, NLAYER * DM, DI, t2);

        long long t3 = (long long)NLAYER * 128 * DI / 4;
        tofp16_xw_kernel<<<(unsigned)((t3 + 255) / 256), 256>>>(x_proj_w);

        long long t4 = (long long)VOCAB_PAD * DM / 4;
        tofp16_kernel<<<(unsigned)((t4 + 255) / 256), 256>>>(
            emb, emb_h, VOCAB, DM, t4);
    }

    for (int i = 0; i < NLAYER; i++) {
        rmsnorm_f16_kernel<<<L_SEQ, 256>>>(h, hn_h, norm_w + (size_t)i * DM);

        // xz = hn @ in_proj_w^T   (1024 x 3072, K=768, 24 chunks)
        {
            dim3 g1(L_SEQ / TCM, 2 * DI / 64, 1);
            mma_gemm<64><<<g1, 128, SMEM64>>>(
                hn_h, inw_h + (size_t)i * 2 * DI * DM,
                xz, 2 * DI, 2 * DI, DM, DM / TCK, 0);
        }

        conv_silu_kernel<<<(L_SEQ * DI) / 256, 256>>>(
            conv_w + (size_t)i * DI * DCONV, conv_b + (size_t)i * DI);

        // dbl = xc @ x_proj_w^T   (K=1536, 48 chunks, split-K=12, cps=4)
        {
            dim3 g2(L_SEQ / TCM, 2, XPJ_SPLITK);
            mma_gemm<64><<<g2, 128, SMEM64>>>(
                y_h, xw_h + (size_t)i * 128 * DI,
                dblp, DBL_W, DBL_W, DI,
                (DI / TCK) / XPJ_SPLITK, (long long)L_SEQ * DBL_W);
        }
        combine_dbl_kernel<<<(L_SEQ * DBL_W) / 256, 256>>>();

        // dt = softplus(dbl[:, :48] @ dt_proj_w^T + b)
        {
            dim3 g3((DI + GBN - 1) / GBN, L_SEQ / GBM);
            gemm_tn<1><<<g3, 256>>>(dbl, DBL_W,
                                    dt_proj_w + (size_t)i * DI * DTRANK, DTRANK,
                                    dt, DI, DI, DTRANK,
                                    dt_proj_b + (size_t)i * DI);
        }

        // chunked selective scan (32 chunks of 32)
        {
            const float* Al = A_log + (size_t)i * DI * DSTATE;
            dim3 gs(DI / 8, NCHUNK);
            scan_pass1_kernel<<<gs, 128>>>(Al);
            scan_fix_kernel<<<(DI * DSTATE) / 256, 256>>>();
            scan_pass2_kernel<<<gs, 128>>>(Al);
        }

        y_epi_kernel<<<(L_SEQ * DI) / 256, 256>>>(D_param + (size_t)i * DI);

        // part[z] = y @ out_proj_w^T  (48 chunks, split-K=6, cps=8)
        {
            dim3 g4(L_SEQ / TCM, DM / 64, OPJ_SPLITK);
            mma_gemm<64><<<g4, 128, SMEM64>>>(
                y_h, outw_h + (size_t)i * DM * DI,
                part, DM, DM, DI,
                (DI / TCK) / OPJ_SPLITK, (long long)L_SEQ * DM);
        }
        combine_h_kernel<<<(L_SEQ * DM) / 256, 256>>>();
    }

    // final rmsnorm -> fp16 hn
    rmsnorm_f16_kernel<<<L_SEQ, 256>>>(h, hn_h, norm_f_w);

    // logits = hn @ emb^T — fp16 GEMM, K=768, TN=128 tile
    {
        dim3 g5(L_SEQ / TCM, VOCAB_PAD / 128, 1);
        mma_gemm<128><<<g5, 256, SMEM128>>>(hn_h, emb_h, logits, VOCAB, VOCAB, DM,
                                            DM / TCK, 0);
    }
}